// round 2
// baseline (speedup 1.0000x reference)
#include <cuda_runtime.h>
#include <cuda_bf16.h>
#include <math.h>
#include <stdint.h>
#include <stddef.h>

#define SS 512
#define DD 1024
#define NNH 4096
#define VV 32000
#define MROWS 1024
#define MMDD (MROWS * DD)
#define EPSLN 1e-5f
#define GRU_CTAS 128

// ---------------- device scratch (no allocations allowed) ----------------
__device__ float  g_x[MROWS * DD];
__device__ float  g_y[MROWS * DD];
__device__ float  g_gi[MROWS * 3 * DD];
__device__ float  g_hid[MROWS * NNH];
__device__ float  g_psum[4 * MROWS * DD];
__device__ float  g_h[2][2 * DD];
__device__ double g_part[10 * 512];
__device__ float  g_scale[10];
__device__ float  g_scaleinv[10];
__device__ unsigned g_bar_cnt;
__device__ unsigned g_bar_phase;

// ---------------- f32x2 helpers ----------------
__device__ __forceinline__ unsigned long long pk2(float x, float y) {
    unsigned long long r;
    asm("mov.b64 %0, {%1, %2};" : "=l"(r) : "f"(x), "f"(y));
    return r;
}
__device__ __forceinline__ void ffma2(unsigned long long& d, unsigned long long a, unsigned long long b) {
    asm("fma.rn.f32x2 %0, %1, %2, %0;" : "+l"(d) : "l"(a), "l"(b));
}
__device__ __forceinline__ float2 unpk(unsigned long long v) {
    float2 f;
    asm("mov.b64 {%0, %1}, %2;" : "=f"(f.x), "=f"(f.y) : "l"(v));
    return f;
}

// ---------------- abs-mean scale (two-stage, double, deterministic) ----------------
__global__ void absmean_part(const float4* __restrict__ src, long n4, int slot) {
    __shared__ double sred[256];
    double acc = 0.0;
    for (long i = (long)blockIdx.x * 256 + threadIdx.x; i < n4; i += (long)gridDim.x * 256) {
        float4 v = src[i];
        acc += (double)(fabsf(v.x) + fabsf(v.y)) + (double)(fabsf(v.z) + fabsf(v.w));
    }
    sred[threadIdx.x] = acc;
    __syncthreads();
#pragma unroll
    for (int o = 128; o > 0; o >>= 1) {
        if ((int)threadIdx.x < o) sred[threadIdx.x] += sred[threadIdx.x + o];
        __syncthreads();
    }
    if (threadIdx.x == 0) g_part[slot * 512 + blockIdx.x] = sred[0];
}

__global__ void absmean_final() {
    __shared__ double sred[256];
    int slot = blockIdx.x;
    int t = threadIdx.x;
    sred[t] = g_part[slot * 512 + t] + g_part[slot * 512 + 256 + t];
    __syncthreads();
#pragma unroll
    for (int o = 128; o > 0; o >>= 1) {
        if (t < o) sred[t] += sred[t + o];
        __syncthreads();
    }
    if (t == 0) {
        double cnt = (slot < 2) ? (double)VV * DD : (double)NNH * DD;
        double s = sred[0] / cnt + 1e-8;
        g_scale[slot]    = (float)s;
        g_scaleinv[slot] = (float)(1.0 / s);
    }
}

// ---------------- embedding: tern(emb)[ids] + pos ----------------
__global__ void embed_kernel(const int* __restrict__ ids, const float* __restrict__ emb,
                             const float* __restrict__ pos, float* __restrict__ x) {
    int i = blockIdx.x * 256 + threadIdx.x;     // 0 .. 2^20-1
    int d = i & (DD - 1);
    int s = (i >> 10) & (SS - 1);
    int b = i >> 19;
    int tok = ids[b * SS + s];
    float w = emb[(size_t)tok * DD + d];
    float tn = g_scale[0] * rintf(fminf(fmaxf(w * g_scaleinv[0], -1.f), 1.f));
    x[i] = tn + pos[s * DD + d];
}

// ---------------- SGEMM NT: C[m,n] = sum_k A[m,k]*B[n,k]  (f32x2) ----------------
template <bool TERN, bool RELU>
__global__ __launch_bounds__(256, 2) void sgemm_nt(
    const float* __restrict__ A, const float* __restrict__ B,
    float* __restrict__ C, const float* __restrict__ bias,
    const float* __restrict__ res, int M, int N, int Kld, int kLen, int scaleIdx)
{
    __shared__ float As[16][132];
    __shared__ float Bs[16][132];
    const int bm = blockIdx.y * 128, bn = blockIdx.x * 128;
    const int t  = threadIdx.x;
    const int tx = t & 15, ty = t >> 4;
    float sc = 1.f, inv = 1.f;
    if (TERN) { sc = g_scale[scaleIdx]; inv = g_scaleinv[scaleIdx]; }
    const int kOff = blockIdx.z * kLen;
    if (gridDim.z > 1) C += (size_t)blockIdx.z * (size_t)M * N;

    const int lr = t >> 1;
    const int lc = (t & 1) * 8;
    const float* Ap = A + (size_t)(bm + lr) * Kld + kOff + lc;
    const float* Bp = B + (size_t)(bn + lr) * Kld + kOff + lc;

    unsigned long long acc[8][4];
#pragma unroll
    for (int i = 0; i < 8; i++)
#pragma unroll
        for (int p = 0; p < 4; p++) acc[i][p] = 0ull;

    float4 a0v = *(const float4*)(Ap);
    float4 a1v = *(const float4*)(Ap + 4);
    float4 b0v = *(const float4*)(Bp);
    float4 b1v = *(const float4*)(Bp + 4);

    for (int k0 = 0; k0 < kLen; k0 += 16) {
        if (TERN) {
            b0v.x = rintf(fminf(fmaxf(b0v.x * inv, -1.f), 1.f));
            b0v.y = rintf(fminf(fmaxf(b0v.y * inv, -1.f), 1.f));
            b0v.z = rintf(fminf(fmaxf(b0v.z * inv, -1.f), 1.f));
            b0v.w = rintf(fminf(fmaxf(b0v.w * inv, -1.f), 1.f));
            b1v.x = rintf(fminf(fmaxf(b1v.x * inv, -1.f), 1.f));
            b1v.y = rintf(fminf(fmaxf(b1v.y * inv, -1.f), 1.f));
            b1v.z = rintf(fminf(fmaxf(b1v.z * inv, -1.f), 1.f));
            b1v.w = rintf(fminf(fmaxf(b1v.w * inv, -1.f), 1.f));
        }
        __syncthreads();
        As[lc + 0][lr] = a0v.x; As[lc + 1][lr] = a0v.y; As[lc + 2][lr] = a0v.z; As[lc + 3][lr] = a0v.w;
        As[lc + 4][lr] = a1v.x; As[lc + 5][lr] = a1v.y; As[lc + 6][lr] = a1v.z; As[lc + 7][lr] = a1v.w;
        Bs[lc + 0][lr] = b0v.x; Bs[lc + 1][lr] = b0v.y; Bs[lc + 2][lr] = b0v.z; Bs[lc + 3][lr] = b0v.w;
        Bs[lc + 4][lr] = b1v.x; Bs[lc + 5][lr] = b1v.y; Bs[lc + 6][lr] = b1v.z; Bs[lc + 7][lr] = b1v.w;
        __syncthreads();
        if (k0 + 16 < kLen) {
            a0v = *(const float4*)(Ap + k0 + 16);
            a1v = *(const float4*)(Ap + k0 + 20);
            b0v = *(const float4*)(Bp + k0 + 16);
            b1v = *(const float4*)(Bp + k0 + 20);
        }
#pragma unroll
        for (int kk = 0; kk < 16; kk++) {
            float4 af0 = *(const float4*)&As[kk][ty * 4];
            float4 af1 = *(const float4*)&As[kk][64 + ty * 4];
            float4 bf0 = *(const float4*)&Bs[kk][tx * 4];
            float4 bf1 = *(const float4*)&Bs[kk][64 + tx * 4];
            unsigned long long bb0 = pk2(bf0.x, bf0.y);
            unsigned long long bb1 = pk2(bf0.z, bf0.w);
            unsigned long long bb2 = pk2(bf1.x, bf1.y);
            unsigned long long bb3 = pk2(bf1.z, bf1.w);
            float am[8] = {af0.x, af0.y, af0.z, af0.w, af1.x, af1.y, af1.z, af1.w};
#pragma unroll
            for (int mi = 0; mi < 8; mi++) {
                unsigned long long aa = pk2(am[mi], am[mi]);
                ffma2(acc[mi][0], aa, bb0);
                ffma2(acc[mi][1], aa, bb1);
                ffma2(acc[mi][2], aa, bb2);
                ffma2(acc[mi][3], aa, bb3);
            }
        }
    }

#pragma unroll
    for (int mi = 0; mi < 8; mi++) {
        int m = bm + ((mi < 4) ? (ty * 4 + mi) : (64 + ty * 4 + mi - 4));
        float* Cp = C + (size_t)m * N + bn;
        const float* Rp = res ? (res + (size_t)m * N + bn) : (const float*)0;
#pragma unroll
        for (int p = 0; p < 4; p++) {
            int nl = (p < 2) ? (tx * 4 + p * 2) : (64 + tx * 4 + (p - 2) * 2);
            float2 c = unpk(acc[mi][p]);
            float v0 = c.x, v1 = c.y;
            if (TERN) { v0 *= sc; v1 *= sc; }
            if (bias) { v0 += bias[bn + nl]; v1 += bias[bn + nl + 1]; }
            if (res)  { v0 += Rp[nl]; v1 += Rp[nl + 1]; }
            if (RELU) { v0 = fmaxf(v0, 0.f); v1 = fmaxf(v1, 0.f); }
            Cp[nl] = v0;
            Cp[nl + 1] = v1;
        }
    }
}

// ---------------- split-K reduce: y = sum_z psum + bias + res ----------------
__global__ void reduce4_kernel(const float* __restrict__ bias, const float* __restrict__ res,
                               float* __restrict__ y) {
    int i = blockIdx.x * 256 + threadIdx.x;
    float v = g_psum[i] + g_psum[MMDD + i] + g_psum[2 * MMDD + i] + g_psum[3 * MMDD + i];
    y[i] = v + bias[i & (DD - 1)] + res[i];
}

// ---------------- LayerNorm (1 block / row) ----------------
__global__ void ln_kernel(const float* __restrict__ in, float* __restrict__ out,
                          const float* __restrict__ gamma, const float* __restrict__ beta)
{
    __shared__ float sred[256];
    const int row = blockIdx.x, t = threadIdx.x;
    const float4 v = ((const float4*)(in + (size_t)row * DD))[t];
    sred[t] = v.x + v.y + v.z + v.w;
    __syncthreads();
#pragma unroll
    for (int o = 128; o > 0; o >>= 1) { if (t < o) sred[t] += sred[t + o]; __syncthreads(); }
    float mean = sred[0] * (1.f / 1024.f);
    __syncthreads();
    float dx = v.x - mean, dy = v.y - mean, dz = v.z - mean, dw = v.w - mean;
    sred[t] = dx * dx + dy * dy + dz * dz + dw * dw;
    __syncthreads();
#pragma unroll
    for (int o = 128; o > 0; o >>= 1) { if (t < o) sred[t] += sred[t + o]; __syncthreads(); }
    float rstd = rsqrtf(sred[0] * (1.f / 1024.f) + EPSLN);
    float4 g = ((const float4*)gamma)[t];
    float4 b = ((const float4*)beta)[t];
    float4 o4;
    o4.x = dx * rstd * g.x + b.x;
    o4.y = dy * rstd * g.y + b.y;
    o4.z = dz * rstd * g.z + b.z;
    o4.w = dw * rstd * g.w + b.w;
    ((float4*)(out + (size_t)row * DD))[t] = o4;
}

// ---------------- grid barrier (phase-flip, replay-safe) ----------------
__device__ __forceinline__ void gbar(unsigned nb) {
    __syncthreads();
    if (threadIdx.x == 0) {
        __threadfence();
        unsigned ph = atomicAdd(&g_bar_phase, 0u);
        unsigned tick = atomicAdd(&g_bar_cnt, 1u);
        if (tick == nb - 1) {
            g_bar_cnt = 0;
            __threadfence();
            atomicExch(&g_bar_phase, ph ^ 1u);
        } else {
            while (atomicAdd(&g_bar_phase, 0u) == ph) { }
        }
        __threadfence();
    }
    __syncthreads();
}

// ---------------- persistent GRU ----------------
__global__ __launch_bounds__(192, 1) void gru_kernel(
    const float* __restrict__ gi, const float* __restrict__ whh,
    const float* __restrict__ bhh, float* __restrict__ x)
{
    extern __shared__ float sm[];
    float* sw  = sm;                    // 24 rows x 1028 (padded)
    float* hs  = sm + 24 * 1028;        // 2 x 1024
    float* sgh = hs + 2048;             // 24 x 2
    float* sbh = sgh + 48;              // 24
    const int tid = threadIdx.x;
    const int base = blockIdx.x * 8;

    // load Whh slice: row r = g*8+dd  <->  whh row g*1024 + base + dd
    for (int idx = tid; idx < 24 * 256; idx += 192) {
        int r = idx >> 8, c4 = idx & 255;
        int g = r >> 3, dd = r & 7;
        float4 w = *(const float4*)(whh + (size_t)(g * 1024 + base + dd) * 1024 + c4 * 4);
        *(float4*)(sw + r * 1028 + c4 * 4) = w;
    }
    if (tid < 24) sbh[tid] = bhh[(tid >> 3) * 1024 + base + (tid & 7)];
    if (tid < 16) g_h[0][(tid & 1) * 1024 + base + (tid >> 1)] = 0.f;
    gbar(GRU_CTAS);

    const int r = tid >> 3, j = tid & 7;
    const float* wrow = sw + r * 1028;

    for (int s = 0; s < SS; s++) {
        const int rb = s & 1, wb = rb ^ 1;
        for (int idx = tid; idx < 512; idx += 192)
            ((float4*)hs)[idx] = __ldcg((const float4*)&g_h[rb][0] + idx);
        __syncthreads();

        float acc0 = 0.f, acc1 = 0.f;
#pragma unroll
        for (int i = 0; i < 32; i++) {
            int c4 = i * 8 + j;
            float4 w  = *(const float4*)(wrow + c4 * 4);
            float4 h0 = ((const float4*)hs)[c4];
            float4 h1 = ((const float4*)hs)[256 + c4];
            acc0 += w.x * h0.x + w.y * h0.y + w.z * h0.z + w.w * h0.w;
            acc1 += w.x * h1.x + w.y * h1.y + w.z * h1.z + w.w * h1.w;
        }
#pragma unroll
        for (int o = 4; o; o >>= 1) {
            acc0 += __shfl_down_sync(0xffffffffu, acc0, o);
            acc1 += __shfl_down_sync(0xffffffffu, acc1, o);
        }
        if (j == 0) { sgh[r * 2] = acc0 + sbh[r]; sgh[r * 2 + 1] = acc1 + sbh[r]; }
        __syncthreads();

        if (tid < 16) {
            int b = tid & 1, dd = tid >> 1;
            int dg = base + dd;
            size_t m = (size_t)b * SS + s;
            const float* gim = gi + m * 3072;
            float ir = gim[dg], iz = gim[1024 + dg], inn = gim[2048 + dg];
            float hr = sgh[dd * 2 + b], hz = sgh[(8 + dd) * 2 + b], hn = sgh[(16 + dd) * 2 + b];
            float rg = 1.f / (1.f + expf(-(ir + hr)));
            float zg = 1.f / (1.f + expf(-(iz + hz)));
            float ng = tanhf(inn + rg * hn);
            float hp = hs[b * 1024 + dg];
            float hv = (1.f - zg) * ng + zg * hp;
            __stcg(&g_h[wb][b * 1024 + dg], hv);
            x[m * 1024 + dg] = hv;
        }
        gbar(GRU_CTAS);
    }
}

// ---------------- launch ----------------
extern "C" void kernel_launch(void* const* d_in, const int* in_sizes, int n_in,
                              void* d_out, int out_size) {
    const int*   ids     = (const int*)  d_in[0];
    const float* emb     = (const float*)d_in[1];
    const float* pos     = (const float*)d_in[2];
    const float* gru_wih = (const float*)d_in[3];
    const float* gru_whh = (const float*)d_in[4];
    const float* gru_bih = (const float*)d_in[5];
    const float* gru_bhh = (const float*)d_in[6];
    const float* syn_w   = (const float*)d_in[7];
    const float* syn_b   = (const float*)d_in[8];
    const float* out_w   = (const float*)d_in[9];
    const float* out_b   = (const float*)d_in[10];
    const float* ln_g    = (const float*)d_in[11];
    const float* ln_b    = (const float*)d_in[12];
    const float* on_g    = (const float*)d_in[13];
    const float* on_b    = (const float*)d_in[14];
    const float* head_w  = (const float*)d_in[15];
    const float* head_b  = (const float*)d_in[16];
    float* logits = (float*)d_out;

    float *xg, *yg, *gig, *hidg, *psg;
    cudaGetSymbolAddress((void**)&xg,   g_x);
    cudaGetSymbolAddress((void**)&yg,   g_y);
    cudaGetSymbolAddress((void**)&gig,  g_gi);
    cudaGetSymbolAddress((void**)&hidg, g_hid);
    cudaGetSymbolAddress((void**)&psg,  g_psum);

    static bool attr_done = false;
    int gru_smem = (24 * 1028 + 2048 + 48 + 24) * 4;
    if (!attr_done) {
        cudaFuncSetAttribute(gru_kernel, cudaFuncAttributeMaxDynamicSharedMemorySize, gru_smem);
        attr_done = true;
    }

    // 1) abs-mean scales: 0=emb, 1=head, 2+l=syn, 6+l=out
    long nVD4 = (long)VV * DD / 4, nND4 = (long)NNH * DD / 4;
    absmean_part<<<512, 256>>>((const float4*)emb,    nVD4, 0);
    absmean_part<<<512, 256>>>((const float4*)head_w, nVD4, 1);
    for (int l = 0; l < 4; l++) {
        absmean_part<<<512, 256>>>((const float4*)(syn_w + (size_t)l * NNH * DD), nND4, 2 + l);
        absmean_part<<<512, 256>>>((const float4*)(out_w + (size_t)l * DD * NNH), nND4, 6 + l);
    }
    absmean_final<<<10, 256>>>();

    // 2) embedding
    embed_kernel<<<4096, 256>>>(ids, emb, pos, xg);

    // 3) GRU input projections: [1024,3072]
    sgemm_nt<false, false><<<dim3(3072 / 128, MROWS / 128, 1), 256>>>(
        xg, gru_wih, gig, gru_bih, (const float*)0, MROWS, 3072, DD, DD, 0);

    // 4) GRU recurrence (persistent)
    gru_kernel<<<GRU_CTAS, 192, gru_smem>>>(gig, gru_whh, gru_bhh, xg);

    // 5) MLP layers
    for (int l = 0; l < 4; l++) {
        sgemm_nt<true, true><<<dim3(NNH / 128, MROWS / 128, 1), 256>>>(
            xg, syn_w + (size_t)l * NNH * DD, hidg, syn_b + (size_t)l * NNH,
            (const float*)0, MROWS, NNH, DD, DD, 2 + l);
        sgemm_nt<true, false><<<dim3(DD / 128, MROWS / 128, 4), 256>>>(
            hidg, out_w + (size_t)l * DD * NNH, psg, (const float*)0,
            (const float*)0, MROWS, DD, NNH, NNH / 4, 6 + l);
        reduce4_kernel<<<MMDD / 256, 256>>>(out_b + (size_t)l * DD, xg, yg);
        ln_kernel<<<MROWS, 256>>>(yg, xg, ln_g + (size_t)l * DD, ln_b + (size_t)l * DD);
    }

    // 6) final LN + head
    ln_kernel<<<MROWS, 256>>>(xg, yg, on_g, on_b);
    sgemm_nt<true, false><<<dim3(VV / 128, MROWS / 128, 1), 256>>>(
        yg, head_w, logits, head_b, (const float*)0, MROWS, VV, DD, DD, 1);
}

// round 3
// speedup vs baseline: 1.4790x; 1.4790x over previous
#include <cuda_runtime.h>
#include <cuda_bf16.h>
#include <math.h>
#include <stdint.h>
#include <stddef.h>

#define SS 512
#define DD 1024
#define NNH 4096
#define VV 32000
#define MROWS 1024
#define MMDD (MROWS * DD)
#define EPSLN 1e-5f
#define GRU_CTAS 128

// ---------------- device scratch ----------------
__device__ float  g_x[MROWS * DD];
__device__ float  g_y[MROWS * DD];
__device__ float  g_gi[MROWS * 3 * DD];
__device__ float  g_psum[4 * MROWS * DD];
__device__ float  g_h[2][2 * DD];
__device__ double g_part[10 * 512];
__device__ float  g_scale[10];
__device__ float  g_scaleinv[10];
__device__ unsigned g_bar_cnt;
__device__ unsigned g_bar_phase;

// bf16 buffers
__device__ __nv_bfloat16 g_qhead[VV * DD];
__device__ __nv_bfloat16 g_qsyn[4 * NNH * DD];
__device__ __nv_bfloat16 g_qout[4 * NNH * DD];
__device__ __nv_bfloat16 g_wihhi[3 * DD * DD];
__device__ __nv_bfloat16 g_wihlo[3 * DD * DD];
__device__ __nv_bfloat16 g_xhi[MROWS * DD],  g_xlo[MROWS * DD];
__device__ __nv_bfloat16 g_yhi[MROWS * DD],  g_ylo[MROWS * DD];
__device__ __nv_bfloat16 g_hhi[MROWS * NNH], g_hlo[MROWS * NNH];

// ---------------- asm helpers ----------------
#define CP16(dst, src) asm volatile("cp.async.cg.shared.global [%0], [%1], 16;" :: "r"(dst), "l"(src))
#define CPCOMMIT() asm volatile("cp.async.commit_group;")
#define CPWAIT1()  asm volatile("cp.async.wait_group 1;")
#define LDSM4(r, addr) asm volatile( \
    "ldmatrix.sync.aligned.m8n8.x4.shared.b16 {%0,%1,%2,%3}, [%4];" \
    : "=r"((r)[0]), "=r"((r)[1]), "=r"((r)[2]), "=r"((r)[3]) : "r"(addr))
#define MMA16816(d, a, b0, b1) asm volatile( \
    "mma.sync.aligned.m16n8k16.row.col.f32.bf16.bf16.f32 " \
    "{%0,%1,%2,%3},{%4,%5,%6,%7},{%8,%9},{%0,%1,%2,%3};" \
    : "+f"((d)[0]), "+f"((d)[1]), "+f"((d)[2]), "+f"((d)[3]) \
    : "r"((a)[0]), "r"((a)[1]), "r"((a)[2]), "r"((a)[3]), "r"(b0), "r"(b1))

__device__ __forceinline__ unsigned short bf16bits(float x) {
    return __bfloat16_as_ushort(__float2bfloat16(x));
}

// ---------------- abs-mean scale ----------------
__global__ void absmean_part(const float4* __restrict__ src, long n4, int slot) {
    __shared__ double sred[256];
    double acc = 0.0;
    for (long i = (long)blockIdx.x * 256 + threadIdx.x; i < n4; i += (long)gridDim.x * 256) {
        float4 v = src[i];
        acc += (double)(fabsf(v.x) + fabsf(v.y)) + (double)(fabsf(v.z) + fabsf(v.w));
    }
    sred[threadIdx.x] = acc;
    __syncthreads();
#pragma unroll
    for (int o = 128; o > 0; o >>= 1) {
        if ((int)threadIdx.x < o) sred[threadIdx.x] += sred[threadIdx.x + o];
        __syncthreads();
    }
    if (threadIdx.x == 0) g_part[slot * 512 + blockIdx.x] = sred[0];
}

__global__ void absmean_final() {
    __shared__ double sred[256];
    int slot = blockIdx.x, t = threadIdx.x;
    sred[t] = g_part[slot * 512 + t] + g_part[slot * 512 + 256 + t];
    __syncthreads();
#pragma unroll
    for (int o = 128; o > 0; o >>= 1) {
        if (t < o) sred[t] += sred[t + o];
        __syncthreads();
    }
    if (t == 0) {
        double cnt = (slot < 2) ? (double)VV * DD : (double)NNH * DD;
        double s = sred[0] / cnt + 1e-8;
        g_scale[slot]    = (float)s;
        g_scaleinv[slot] = (float)(1.0 / s);
    }
}

// ---------------- weight quantization ----------------
__global__ void tern_quant(const float4* __restrict__ w, ushort4* __restrict__ q,
                           int slot, int n4) {
    int i = blockIdx.x * 256 + threadIdx.x;
    if (i >= n4) return;
    float inv = g_scaleinv[slot];
    float4 v = w[i];
    ushort4 o;
    o.x = bf16bits(rintf(fminf(fmaxf(v.x * inv, -1.f), 1.f)));
    o.y = bf16bits(rintf(fminf(fmaxf(v.y * inv, -1.f), 1.f)));
    o.z = bf16bits(rintf(fminf(fmaxf(v.z * inv, -1.f), 1.f)));
    o.w = bf16bits(rintf(fminf(fmaxf(v.w * inv, -1.f), 1.f)));
    q[i] = o;
}

__global__ void hilo_quant(const float4* __restrict__ w, ushort4* __restrict__ hi,
                           ushort4* __restrict__ lo, int n4) {
    int i = blockIdx.x * 256 + threadIdx.x;
    if (i >= n4) return;
    float4 v = w[i];
    ushort4 h, l;
    float f;
    __nv_bfloat16 hb;
    hb = __float2bfloat16(v.x); f = v.x - __bfloat162float(hb); h.x = __bfloat16_as_ushort(hb); l.x = bf16bits(f);
    hb = __float2bfloat16(v.y); f = v.y - __bfloat162float(hb); h.y = __bfloat16_as_ushort(hb); l.y = bf16bits(f);
    hb = __float2bfloat16(v.z); f = v.z - __bfloat162float(hb); h.z = __bfloat16_as_ushort(hb); l.z = bf16bits(f);
    hb = __float2bfloat16(v.w); f = v.w - __bfloat162float(hb); h.w = __bfloat16_as_ushort(hb); l.w = bf16bits(f);
    hi[i] = h; lo[i] = l;
}

// ---------------- embedding ----------------
__global__ void embed_kernel(const int* __restrict__ ids, const float* __restrict__ emb,
                             const float* __restrict__ pos, float* __restrict__ x,
                             __nv_bfloat16* __restrict__ xhi, __nv_bfloat16* __restrict__ xlo) {
    int i = blockIdx.x * 256 + threadIdx.x;
    int d = i & (DD - 1);
    int s = (i >> 10) & (SS - 1);
    int b = i >> 19;
    int tok = ids[b * SS + s];
    float w = emb[(size_t)tok * DD + d];
    float tn = g_scale[0] * rintf(fminf(fmaxf(w * g_scaleinv[0], -1.f), 1.f));
    float v = tn + pos[s * DD + d];
    x[i] = v;
    __nv_bfloat16 h = __float2bfloat16(v);
    xhi[i] = h;
    xlo[i] = __float2bfloat16(v - __bfloat162float(h));
}

// ---------------- x -> hi/lo ----------------
__global__ void xhilo_kernel(const float* __restrict__ x,
                             __nv_bfloat16* __restrict__ hi, __nv_bfloat16* __restrict__ lo) {
    int i = blockIdx.x * 256 + threadIdx.x;
    float v = x[i];
    __nv_bfloat16 h = __float2bfloat16(v);
    hi[i] = h;
    lo[i] = __float2bfloat16(v - __bfloat162float(h));
}

// ---------------- bf16 tensor-core GEMM NT ----------------
// C[m,n] = sum_k A[m,k]*B[n,k]; A given as hi/lo bf16.
// MODE 0: B = single (ternary exact) buffer: 2 mma passes (Ahi*B + Alo*B)
// MODE 1: B = hi/lo: 3 passes (Ahi*Bhi + Alo*Bhi + Ahi*Blo)
template<int MODE, bool TERN, bool RELU, bool OUT_HILO>
__global__ __launch_bounds__(256) void bgemm(
    const __nv_bfloat16* __restrict__ Ahi, const __nv_bfloat16* __restrict__ Alo,
    const __nv_bfloat16* __restrict__ Bhi, const __nv_bfloat16* __restrict__ Blo,
    float* __restrict__ C, __nv_bfloat16* __restrict__ Chi, __nv_bfloat16* __restrict__ Clo,
    const float* __restrict__ bias, const float* __restrict__ res,
    int M, int N, int Kld, int kLen, int scaleIdx)
{
    constexpr int SZ = 128 * 40;  // bf16 elems per stage per matrix
    extern __shared__ __align__(16) __nv_bfloat16 smb[];
    __nv_bfloat16* sAhi = smb;
    __nv_bfloat16* sAlo = smb + 2 * SZ;
    __nv_bfloat16* sBhi = smb + 4 * SZ;
    __nv_bfloat16* sBlo = smb + 6 * SZ;   // MODE 1 only

    const int t = threadIdx.x;
    const int lane = t & 31;
    const int w = t >> 5;
    const int warpM = (w >> 1) << 5;   // 0..96
    const int warpN = (w & 1) << 6;    // 0,64
    const int bm = blockIdx.y << 7, bn = blockIdx.x << 7;
    const int kOff = blockIdx.z * kLen;
    if (gridDim.z > 1) C += (size_t)blockIdx.z * ((size_t)M * N);

    const __nv_bfloat16* gAhi = Ahi + (size_t)bm * Kld + kOff;
    const __nv_bfloat16* gAlo = Alo + (size_t)bm * Kld + kOff;
    const __nv_bfloat16* gBhi = Bhi + (size_t)bn * Kld + kOff;
    const __nv_bfloat16* gBlo = (MODE == 1) ? (Blo + (size_t)bn * Kld + kOff) : (const __nv_bfloat16*)0;

    const unsigned uAhi = (unsigned)__cvta_generic_to_shared(sAhi);
    const unsigned uAlo = (unsigned)__cvta_generic_to_shared(sAlo);
    const unsigned uBhi = (unsigned)__cvta_generic_to_shared(sBhi);
    const unsigned uBlo = (MODE == 1) ? (unsigned)__cvta_generic_to_shared(sBlo) : 0u;

    const int lrow = t >> 2;
    const int lcol = (t & 3) << 3;

    float acc[2][8][4];
#pragma unroll
    for (int i = 0; i < 2; i++)
#pragma unroll
        for (int j = 0; j < 8; j++)
#pragma unroll
            for (int p = 0; p < 4; p++) acc[i][j][p] = 0.f;

    const int NS = kLen >> 5;

    // prologue: stage 0 -> buf 0
    {
#pragma unroll
        for (int h = 0; h < 2; h++) {
            int row = lrow + (h << 6);
            size_t go = (size_t)row * Kld + lcol;
            unsigned so = ((unsigned)(row * 40 + lcol) << 1);
            CP16(uAhi + so, gAhi + go);
            CP16(uAlo + so, gAlo + go);
            CP16(uBhi + so, gBhi + go);
            if (MODE == 1) CP16(uBlo + so, gBlo + go);
        }
        CPCOMMIT();
    }

    for (int s = 0; s < NS; s++) {
        if (s + 1 < NS) {
            int k0 = (s + 1) << 5, buf = (s + 1) & 1;
#pragma unroll
            for (int h = 0; h < 2; h++) {
                int row = lrow + (h << 6);
                size_t go = (size_t)row * Kld + k0 + lcol;
                unsigned so = ((unsigned)(row * 40 + lcol) << 1) + (unsigned)buf * (SZ << 1);
                CP16(uAhi + so, gAhi + go);
                CP16(uAlo + so, gAlo + go);
                CP16(uBhi + so, gBhi + go);
                if (MODE == 1) CP16(uBlo + so, gBlo + go);
            }
        }
        CPCOMMIT();
        CPWAIT1();
        __syncthreads();

        unsigned bufOff = (unsigned)(s & 1) * (SZ << 1);
#pragma unroll
        for (int kk = 0; kk < 32; kk += 16) {
            uint32_t ah[2][4], al[2][4], bh[4][4], bl[4][4];
#pragma unroll
            for (int mt = 0; mt < 2; mt++) {
                unsigned ra = ((unsigned)((warpM + (mt << 4) + (lane & 15)) * 40 + kk + ((lane >> 4) << 3)) << 1) + bufOff;
                LDSM4(ah[mt], uAhi + ra);
                LDSM4(al[mt], uAlo + ra);
            }
#pragma unroll
            for (int bj = 0; bj < 4; bj++) {
                unsigned rb = ((unsigned)((warpN + (bj << 4) + ((lane >> 4) << 3) + (lane & 7)) * 40 + kk + (((lane >> 3) & 1) << 3)) << 1) + bufOff;
                LDSM4(bh[bj], uBhi + rb);
                if (MODE == 1) LDSM4(bl[bj], uBlo + rb);
            }
#pragma unroll
            for (int mt = 0; mt < 2; mt++)
#pragma unroll
                for (int nt = 0; nt < 8; nt++) {
                    uint32_t b0 = bh[nt >> 1][(nt & 1) << 1];
                    uint32_t b1 = bh[nt >> 1][((nt & 1) << 1) + 1];
                    MMA16816(acc[mt][nt], ah[mt], b0, b1);
                    MMA16816(acc[mt][nt], al[mt], b0, b1);
                    if (MODE == 1) {
                        uint32_t c0 = bl[nt >> 1][(nt & 1) << 1];
                        uint32_t c1 = bl[nt >> 1][((nt & 1) << 1) + 1];
                        MMA16816(acc[mt][nt], ah[mt], c0, c1);
                    }
                }
        }
        __syncthreads();
    }

    float sc = TERN ? g_scale[scaleIdx] : 1.f;
#pragma unroll
    for (int mt = 0; mt < 2; mt++)
#pragma unroll
        for (int nt = 0; nt < 8; nt++) {
            int row = bm + warpM + (mt << 4) + (lane >> 2);
            int col = bn + warpN + (nt << 3) + ((lane & 3) << 1);
#pragma unroll
            for (int half = 0; half < 2; half++) {
                int r = row + half * 8;
                float v0 = acc[mt][nt][half * 2 + 0];
                float v1 = acc[mt][nt][half * 2 + 1];
                if (TERN) { v0 *= sc; v1 *= sc; }
                if (bias) { v0 += bias[col]; v1 += bias[col + 1]; }
                if (res)  { v0 += res[(size_t)r * N + col]; v1 += res[(size_t)r * N + col + 1]; }
                if (RELU) { v0 = fmaxf(v0, 0.f); v1 = fmaxf(v1, 0.f); }
                if (OUT_HILO) {
                    __nv_bfloat16 h0 = __float2bfloat16(v0);
                    __nv_bfloat16 h1 = __float2bfloat16(v1);
                    Chi[(size_t)r * N + col]     = h0;
                    Chi[(size_t)r * N + col + 1] = h1;
                    Clo[(size_t)r * N + col]     = __float2bfloat16(v0 - __bfloat162float(h0));
                    Clo[(size_t)r * N + col + 1] = __float2bfloat16(v1 - __bfloat162float(h1));
                } else {
                    C[(size_t)r * N + col]     = v0;
                    C[(size_t)r * N + col + 1] = v1;
                }
            }
        }
}

// ---------------- split-K reduce ----------------
__global__ void reduce4_kernel(const float* __restrict__ bias, const float* __restrict__ res,
                               float* __restrict__ y) {
    int i = blockIdx.x * 256 + threadIdx.x;
    float v = g_psum[i] + g_psum[MMDD + i] + g_psum[2 * MMDD + i] + g_psum[3 * MMDD + i];
    y[i] = v + bias[i & (DD - 1)] + res[i];
}

// ---------------- LayerNorm (fp32 out + hi/lo bf16 out) ----------------
__global__ void ln_kernel(const float* __restrict__ in, float* __restrict__ out,
                          __nv_bfloat16* __restrict__ ohi, __nv_bfloat16* __restrict__ olo,
                          const float* __restrict__ gamma, const float* __restrict__ beta)
{
    __shared__ float sred[256];
    const int row = blockIdx.x, t = threadIdx.x;
    const float4 v = ((const float4*)(in + (size_t)row * DD))[t];
    sred[t] = v.x + v.y + v.z + v.w;
    __syncthreads();
#pragma unroll
    for (int o = 128; o > 0; o >>= 1) { if (t < o) sred[t] += sred[t + o]; __syncthreads(); }
    float mean = sred[0] * (1.f / 1024.f);
    __syncthreads();
    float dx = v.x - mean, dy = v.y - mean, dz = v.z - mean, dw = v.w - mean;
    sred[t] = dx * dx + dy * dy + dz * dz + dw * dw;
    __syncthreads();
#pragma unroll
    for (int o = 128; o > 0; o >>= 1) { if (t < o) sred[t] += sred[t + o]; __syncthreads(); }
    float rstd = rsqrtf(sred[0] * (1.f / 1024.f) + EPSLN);
    float4 g = ((const float4*)gamma)[t];
    float4 b = ((const float4*)beta)[t];
    float4 o4;
    o4.x = dx * rstd * g.x + b.x;
    o4.y = dy * rstd * g.y + b.y;
    o4.z = dz * rstd * g.z + b.z;
    o4.w = dw * rstd * g.w + b.w;
    ((float4*)(out + (size_t)row * DD))[t] = o4;
    ushort4 h, l;
    __nv_bfloat16 hb;
    hb = __float2bfloat16(o4.x); h.x = __bfloat16_as_ushort(hb); l.x = bf16bits(o4.x - __bfloat162float(hb));
    hb = __float2bfloat16(o4.y); h.y = __bfloat16_as_ushort(hb); l.y = bf16bits(o4.y - __bfloat162float(hb));
    hb = __float2bfloat16(o4.z); h.z = __bfloat16_as_ushort(hb); l.z = bf16bits(o4.z - __bfloat162float(hb));
    hb = __float2bfloat16(o4.w); h.w = __bfloat16_as_ushort(hb); l.w = bf16bits(o4.w - __bfloat162float(hb));
    ((ushort4*)(ohi + (size_t)row * DD))[t] = h;
    ((ushort4*)(olo + (size_t)row * DD))[t] = l;
}

// ---------------- grid barrier ----------------
__device__ __forceinline__ void gbar(unsigned nb) {
    __syncthreads();
    if (threadIdx.x == 0) {
        __threadfence();
        unsigned ph = atomicAdd(&g_bar_phase, 0u);
        unsigned tick = atomicAdd(&g_bar_cnt, 1u);
        if (tick == nb - 1) {
            g_bar_cnt = 0;
            __threadfence();
            atomicExch(&g_bar_phase, ph ^ 1u);
        } else {
            while (atomicAdd(&g_bar_phase, 0u) == ph) { }
        }
        __threadfence();
    }
    __syncthreads();
}

// ---------------- persistent GRU ----------------
__global__ __launch_bounds__(192, 1) void gru_kernel(
    const float* __restrict__ gi, const float* __restrict__ whh,
    const float* __restrict__ bhh, float* __restrict__ x)
{
    extern __shared__ float sm[];
    float* sw  = sm;
    float* hs  = sm + 24 * 1028;
    float* sgh = hs + 2048;
    float* sbh = sgh + 48;
    const int tid = threadIdx.x;
    const int base = blockIdx.x * 8;

    for (int idx = tid; idx < 24 * 256; idx += 192) {
        int r = idx >> 8, c4 = idx & 255;
        int g = r >> 3, dd = r & 7;
        float4 w = *(const float4*)(whh + (size_t)(g * 1024 + base + dd) * 1024 + c4 * 4);
        *(float4*)(sw + r * 1028 + c4 * 4) = w;
    }
    if (tid < 24) sbh[tid] = bhh[(tid >> 3) * 1024 + base + (tid & 7)];
    if (tid < 16) g_h[0][(tid & 1) * 1024 + base + (tid >> 1)] = 0.f;
    gbar(GRU_CTAS);

    const int r = tid >> 3, j = tid & 7;
    const float* wrow = sw + r * 1028;

    for (int s = 0; s < SS; s++) {
        const int rb = s & 1, wb = rb ^ 1;
        for (int idx = tid; idx < 512; idx += 192)
            ((float4*)hs)[idx] = __ldcg((const float4*)&g_h[rb][0] + idx);
        __syncthreads();

        float acc0 = 0.f, acc1 = 0.f;
#pragma unroll
        for (int i = 0; i < 32; i++) {
            int c4 = i * 8 + j;
            float4 w  = *(const float4*)(wrow + c4 * 4);
            float4 h0 = ((const float4*)hs)[c4];
            float4 h1 = ((const float4*)hs)[256 + c4];
            acc0 += w.x * h0.x + w.y * h0.y + w.z * h0.z + w.w * h0.w;
            acc1 += w.x * h1.x + w.y * h1.y + w.z * h1.z + w.w * h1.w;
        }
#pragma unroll
        for (int o = 4; o; o >>= 1) {
            acc0 += __shfl_down_sync(0xffffffffu, acc0, o);
            acc1 += __shfl_down_sync(0xffffffffu, acc1, o);
        }
        if (j == 0) { sgh[r * 2] = acc0 + sbh[r]; sgh[r * 2 + 1] = acc1 + sbh[r]; }
        __syncthreads();

        if (tid < 16) {
            int b = tid & 1, dd = tid >> 1;
            int dg = base + dd;
            size_t m = (size_t)b * SS + s;
            const float* gim = gi + m * 3072;
            float ir = gim[dg], iz = gim[1024 + dg], inn = gim[2048 + dg];
            float hr = sgh[dd * 2 + b], hz = sgh[(8 + dd) * 2 + b], hn = sgh[(16 + dd) * 2 + b];
            float rg = 1.f / (1.f + expf(-(ir + hr)));
            float zg = 1.f / (1.f + expf(-(iz + hz)));
            float ng = tanhf(inn + rg * hn);
            float hp = hs[b * 1024 + dg];
            float hv = (1.f - zg) * ng + zg * hp;
            __stcg(&g_h[wb][b * 1024 + dg], hv);
            x[m * 1024 + dg] = hv;
        }
        gbar(GRU_CTAS);
    }
}

// ---------------- launch ----------------
extern "C" void kernel_launch(void* const* d_in, const int* in_sizes, int n_in,
                              void* d_out, int out_size) {
    const int*   ids     = (const int*)  d_in[0];
    const float* emb     = (const float*)d_in[1];
    const float* pos     = (const float*)d_in[2];
    const float* gru_wih = (const float*)d_in[3];
    const float* gru_whh = (const float*)d_in[4];
    const float* gru_bih = (const float*)d_in[5];
    const float* gru_bhh = (const float*)d_in[6];
    const float* syn_w   = (const float*)d_in[7];
    const float* syn_b   = (const float*)d_in[8];
    const float* out_w   = (const float*)d_in[9];
    const float* out_b   = (const float*)d_in[10];
    const float* ln_g    = (const float*)d_in[11];
    const float* ln_b    = (const float*)d_in[12];
    const float* on_g    = (const float*)d_in[13];
    const float* on_b    = (const float*)d_in[14];
    const float* head_w  = (const float*)d_in[15];
    const float* head_b  = (const float*)d_in[16];
    float* logits = (float*)d_out;

    float *xg, *yg, *gig, *psg;
    __nv_bfloat16 *qhead, *qsyn, *qout, *wihhi, *wihlo, *xhi, *xlo, *yhi, *ylo, *hhi, *hlo;
    cudaGetSymbolAddress((void**)&xg,   g_x);
    cudaGetSymbolAddress((void**)&yg,   g_y);
    cudaGetSymbolAddress((void**)&gig,  g_gi);
    cudaGetSymbolAddress((void**)&psg,  g_psum);
    cudaGetSymbolAddress((void**)&qhead, g_qhead);
    cudaGetSymbolAddress((void**)&qsyn,  g_qsyn);
    cudaGetSymbolAddress((void**)&qout,  g_qout);
    cudaGetSymbolAddress((void**)&wihhi, g_wihhi);
    cudaGetSymbolAddress((void**)&wihlo, g_wihlo);
    cudaGetSymbolAddress((void**)&xhi, g_xhi);
    cudaGetSymbolAddress((void**)&xlo, g_xlo);
    cudaGetSymbolAddress((void**)&yhi, g_yhi);
    cudaGetSymbolAddress((void**)&ylo, g_ylo);
    cudaGetSymbolAddress((void**)&hhi, g_hhi);
    cudaGetSymbolAddress((void**)&hlo, g_hlo);

    static bool attr_done = false;
    int gru_smem = (24 * 1028 + 2048 + 48 + 24) * 4;
    if (!attr_done) {
        cudaFuncSetAttribute(gru_kernel, cudaFuncAttributeMaxDynamicSharedMemorySize, gru_smem);
        cudaFuncSetAttribute(bgemm<1, false, false, false>, cudaFuncAttributeMaxDynamicSharedMemorySize, 81920);
        cudaFuncSetAttribute(bgemm<0, true, true,  true >, cudaFuncAttributeMaxDynamicSharedMemorySize, 61440);
        cudaFuncSetAttribute(bgemm<0, true, false, false>, cudaFuncAttributeMaxDynamicSharedMemorySize, 61440);
        attr_done = true;
    }

    // 1) abs-mean scales: 0=emb, 1=head, 2+l=syn, 6+l=out
    long nVD4 = (long)VV * DD / 4, nND4 = (long)NNH * DD / 4;
    absmean_part<<<512, 256>>>((const float4*)emb,    nVD4, 0);
    absmean_part<<<512, 256>>>((const float4*)head_w, nVD4, 1);
    for (int l = 0; l < 4; l++) {
        absmean_part<<<512, 256>>>((const float4*)(syn_w + (size_t)l * NNH * DD), nND4, 2 + l);
        absmean_part<<<512, 256>>>((const float4*)(out_w + (size_t)l * DD * NNH), nND4, 6 + l);
    }
    absmean_final<<<10, 256>>>();

    // 2) quantize weights
    tern_quant<<<(int)(nVD4 / 256), 256>>>((const float4*)head_w, (ushort4*)qhead, 1, (int)nVD4);
    for (int l = 0; l < 4; l++) {
        tern_quant<<<(int)(nND4 / 256), 256>>>((const float4*)(syn_w + (size_t)l * NNH * DD),
                                               (ushort4*)(qsyn + (size_t)l * NNH * DD), 2 + l, (int)nND4);
        tern_quant<<<(int)(nND4 / 256), 256>>>((const float4*)(out_w + (size_t)l * DD * NNH),
                                               (ushort4*)(qout + (size_t)l * DD * NNH), 6 + l, (int)nND4);
    }
    int n4wih = 3 * DD * DD / 4;
    hilo_quant<<<n4wih / 256, 256>>>((const float4*)gru_wih, (ushort4*)wihhi, (ushort4*)wihlo, n4wih);

    // 3) embedding (+ hi/lo)
    embed_kernel<<<4096, 256>>>(ids, emb, pos, xg, xhi, xlo);

    // 4) GRU input projections
    bgemm<1, false, false, false><<<dim3(3072 / 128, MROWS / 128, 1), 256, 81920>>>(
        xhi, xlo, wihhi, wihlo, gig, (__nv_bfloat16*)0, (__nv_bfloat16*)0,
        gru_bih, (const float*)0, MROWS, 3072, DD, DD, 0);

    // 5) GRU recurrence
    gru_kernel<<<GRU_CTAS, 192, gru_smem>>>(gig, gru_whh, gru_bhh, xg);
    xhilo_kernel<<<MMDD / 256, 256>>>(xg, xhi, xlo);

    // 6) MLP layers
    for (int l = 0; l < 4; l++) {
        bgemm<0, true, true, true><<<dim3(NNH / 128, MROWS / 128, 1), 256, 61440>>>(
            xhi, xlo, qsyn + (size_t)l * NNH * DD, (const __nv_bfloat16*)0,
            (float*)0, hhi, hlo, syn_b + (size_t)l * NNH, (const float*)0,
            MROWS, NNH, DD, DD, 2 + l);
        bgemm<0, true, false, false><<<dim3(DD / 128, MROWS / 128, 4), 256, 61440>>>(
            hhi, hlo, qout + (size_t)l * DD * NNH, (const __nv_bfloat16*)0,
            psg, (__nv_bfloat16*)0, (__nv_bfloat16*)0, (const float*)0, (const float*)0,
            MROWS, DD, NNH, NNH / 4, 6 + l);
        reduce4_kernel<<<MMDD / 256, 256>>>(out_b + (size_t)l * DD, xg, yg);
        ln_kernel<<<MROWS, 256>>>(yg, xg, xhi, xlo, ln_g + (size_t)l * DD, ln_b + (size_t)l * DD);
    }

    // 7) final LN + head
    ln_kernel<<<MROWS, 256>>>(xg, yg, yhi, ylo, on_g, on_b);
    bgemm<0, true, false, false><<<dim3(VV / 128, MROWS / 128, 1), 256, 61440>>>(
        yhi, ylo, qhead, (const __nv_bfloat16*)0,
        logits, (__nv_bfloat16*)0, (__nv_bfloat16*)0, head_b, (const float*)0,
        MROWS, VV, DD, DD, 1);
}

// round 4
// speedup vs baseline: 1.4965x; 1.0118x over previous
#include <cuda_runtime.h>
#include <cuda_bf16.h>
#include <math.h>
#include <stdint.h>
#include <stddef.h>

#define SS 512
#define DD 1024
#define NNH 4096
#define VV 32000
#define MROWS 1024
#define MMDD (MROWS * DD)
#define EPSLN 1e-5f
#define GRU_CTAS 128

// ---------------- device scratch ----------------
__device__ float  g_x[MROWS * DD];
__device__ float  g_y[MROWS * DD];
__device__ float  g_gi[MROWS * 3 * DD];
__device__ float  g_psum[4 * MROWS * DD];
__device__ float  g_h[2][2 * DD];          // interleaved: [buf][2*d + b]
__device__ double g_part[10 * 512];
__device__ float  g_scale[10];
__device__ float  g_scaleinv[10];
__device__ unsigned g_bar_cnt;
__device__ unsigned g_bar_phase;
__device__ unsigned g_ack;

// bf16 buffers
__device__ __nv_bfloat16 g_qhead[VV * DD];
__device__ __nv_bfloat16 g_qsyn[4 * NNH * DD];
__device__ __nv_bfloat16 g_qout[4 * NNH * DD];
__device__ __nv_bfloat16 g_wihhi[3 * DD * DD];
__device__ __nv_bfloat16 g_wihlo[3 * DD * DD];
__device__ __nv_bfloat16 g_xhi[MROWS * DD],  g_xlo[MROWS * DD];
__device__ __nv_bfloat16 g_yhi[MROWS * DD],  g_ylo[MROWS * DD];
__device__ __nv_bfloat16 g_hhi[MROWS * NNH], g_hlo[MROWS * NNH];

// ---------------- asm helpers ----------------
#define CP16(dst, src) asm volatile("cp.async.cg.shared.global [%0], [%1], 16;" :: "r"(dst), "l"(src))
#define CPCOMMIT() asm volatile("cp.async.commit_group;")
#define CPWAIT1()  asm volatile("cp.async.wait_group 1;")
#define LDSM4(r, addr) asm volatile( \
    "ldmatrix.sync.aligned.m8n8.x4.shared.b16 {%0,%1,%2,%3}, [%4];" \
    : "=r"((r)[0]), "=r"((r)[1]), "=r"((r)[2]), "=r"((r)[3]) : "r"(addr))
#define MMA16816(d, a, b0, b1) asm volatile( \
    "mma.sync.aligned.m16n8k16.row.col.f32.bf16.bf16.f32 " \
    "{%0,%1,%2,%3},{%4,%5,%6,%7},{%8,%9},{%0,%1,%2,%3};" \
    : "+f"((d)[0]), "+f"((d)[1]), "+f"((d)[2]), "+f"((d)[3]) \
    : "r"((a)[0]), "r"((a)[1]), "r"((a)[2]), "r"((a)[3]), "r"(b0), "r"(b1))

__device__ __forceinline__ unsigned short bf16bits(float x) {
    return __bfloat16_as_ushort(__float2bfloat16(x));
}
__device__ __forceinline__ unsigned long long pk2(float x, float y) {
    unsigned long long r;
    asm("mov.b64 %0, {%1, %2};" : "=l"(r) : "f"(x), "f"(y));
    return r;
}
__device__ __forceinline__ void ffma2(unsigned long long& d, unsigned long long a, unsigned long long b) {
    asm("fma.rn.f32x2 %0, %1, %2, %0;" : "+l"(d) : "l"(a), "l"(b));
}
__device__ __forceinline__ float2 unpk(unsigned long long v) {
    float2 f;
    asm("mov.b64 {%0, %1}, %2;" : "=f"(f.x), "=f"(f.y) : "l"(v));
    return f;
}

// ---------------- abs-mean scale (4 independent chains, deterministic) ----------------
__global__ void absmean_part(const float4* __restrict__ src, long n4, int slot) {
    __shared__ double sred[256];
    double a0 = 0.0, a1 = 0.0, a2 = 0.0, a3 = 0.0;
    const long stride = (long)gridDim.x * 256;
    long i = (long)blockIdx.x * 256 + threadIdx.x;
    for (; i + 3 * stride < n4; i += 4 * stride) {
        float4 v0 = src[i];
        float4 v1 = src[i + stride];
        float4 v2 = src[i + 2 * stride];
        float4 v3 = src[i + 3 * stride];
        a0 += (double)(fabsf(v0.x) + fabsf(v0.y)) + (double)(fabsf(v0.z) + fabsf(v0.w));
        a1 += (double)(fabsf(v1.x) + fabsf(v1.y)) + (double)(fabsf(v1.z) + fabsf(v1.w));
        a2 += (double)(fabsf(v2.x) + fabsf(v2.y)) + (double)(fabsf(v2.z) + fabsf(v2.w));
        a3 += (double)(fabsf(v3.x) + fabsf(v3.y)) + (double)(fabsf(v3.z) + fabsf(v3.w));
    }
    for (; i < n4; i += stride) {
        float4 v = src[i];
        a0 += (double)(fabsf(v.x) + fabsf(v.y)) + (double)(fabsf(v.z) + fabsf(v.w));
    }
    sred[threadIdx.x] = (a0 + a1) + (a2 + a3);
    __syncthreads();
#pragma unroll
    for (int o = 128; o > 0; o >>= 1) {
        if ((int)threadIdx.x < o) sred[threadIdx.x] += sred[threadIdx.x + o];
        __syncthreads();
    }
    if (threadIdx.x == 0) g_part[slot * 512 + blockIdx.x] = sred[0];
}

__global__ void absmean_final() {
    __shared__ double sred[256];
    int slot = blockIdx.x, t = threadIdx.x;
    sred[t] = g_part[slot * 512 + t] + g_part[slot * 512 + 256 + t];
    __syncthreads();
#pragma unroll
    for (int o = 128; o > 0; o >>= 1) {
        if (t < o) sred[t] += sred[t + o];
        __syncthreads();
    }
    if (t == 0) {
        double cnt = (slot < 2) ? (double)VV * DD : (double)NNH * DD;
        double s = sred[0] / cnt + 1e-8;
        g_scale[slot]    = (float)s;
        g_scaleinv[slot] = (float)(1.0 / s);
    }
}

// ---------------- weight quantization ----------------
__global__ void tern_quant(const float4* __restrict__ w, ushort4* __restrict__ q,
                           int slot, int n4) {
    int i = blockIdx.x * 256 + threadIdx.x;
    if (i >= n4) return;
    float inv = g_scaleinv[slot];
    float4 v = w[i];
    ushort4 o;
    o.x = bf16bits(rintf(fminf(fmaxf(v.x * inv, -1.f), 1.f)));
    o.y = bf16bits(rintf(fminf(fmaxf(v.y * inv, -1.f), 1.f)));
    o.z = bf16bits(rintf(fminf(fmaxf(v.z * inv, -1.f), 1.f)));
    o.w = bf16bits(rintf(fminf(fmaxf(v.w * inv, -1.f), 1.f)));
    q[i] = o;
}

__global__ void hilo_quant(const float4* __restrict__ w, ushort4* __restrict__ hi,
                           ushort4* __restrict__ lo, int n4) {
    int i = blockIdx.x * 256 + threadIdx.x;
    if (i >= n4) return;
    float4 v = w[i];
    ushort4 h, l;
    __nv_bfloat16 hb;
    hb = __float2bfloat16(v.x); h.x = __bfloat16_as_ushort(hb); l.x = bf16bits(v.x - __bfloat162float(hb));
    hb = __float2bfloat16(v.y); h.y = __bfloat16_as_ushort(hb); l.y = bf16bits(v.y - __bfloat162float(hb));
    hb = __float2bfloat16(v.z); h.z = __bfloat16_as_ushort(hb); l.z = bf16bits(v.z - __bfloat162float(hb));
    hb = __float2bfloat16(v.w); h.w = __bfloat16_as_ushort(hb); l.w = bf16bits(v.w - __bfloat162float(hb));
    hi[i] = h; lo[i] = l;
}

// ---------------- embedding ----------------
__global__ void embed_kernel(const int* __restrict__ ids, const float* __restrict__ emb,
                             const float* __restrict__ pos, float* __restrict__ x,
                             __nv_bfloat16* __restrict__ xhi, __nv_bfloat16* __restrict__ xlo) {
    int i = blockIdx.x * 256 + threadIdx.x;
    int d = i & (DD - 1);
    int s = (i >> 10) & (SS - 1);
    int b = i >> 19;
    int tok = ids[b * SS + s];
    float w = emb[(size_t)tok * DD + d];
    float tn = g_scale[0] * rintf(fminf(fmaxf(w * g_scaleinv[0], -1.f), 1.f));
    float v = tn + pos[s * DD + d];
    x[i] = v;
    __nv_bfloat16 h = __float2bfloat16(v);
    xhi[i] = h;
    xlo[i] = __float2bfloat16(v - __bfloat162float(h));
}

// ---------------- bf16 tensor-core GEMM NT ----------------
template<int MODE, bool TERN, bool RELU, bool OUT_HILO>
__global__ __launch_bounds__(256) void bgemm(
    const __nv_bfloat16* __restrict__ Ahi, const __nv_bfloat16* __restrict__ Alo,
    const __nv_bfloat16* __restrict__ Bhi, const __nv_bfloat16* __restrict__ Blo,
    float* __restrict__ C, __nv_bfloat16* __restrict__ Chi, __nv_bfloat16* __restrict__ Clo,
    const float* __restrict__ bias, const float* __restrict__ res,
    int M, int N, int Kld, int kLen, int scaleIdx)
{
    constexpr int SZ = 128 * 40;
    extern __shared__ __align__(16) __nv_bfloat16 smb[];
    __nv_bfloat16* sAhi = smb;
    __nv_bfloat16* sAlo = smb + 2 * SZ;
    __nv_bfloat16* sBhi = smb + 4 * SZ;
    __nv_bfloat16* sBlo = smb + 6 * SZ;

    const int t = threadIdx.x;
    const int lane = t & 31;
    const int w = t >> 5;
    const int warpM = (w >> 1) << 5;
    const int warpN = (w & 1) << 6;
    const int bm = blockIdx.y << 7, bn = blockIdx.x << 7;
    const int kOff = blockIdx.z * kLen;
    if (gridDim.z > 1) C += (size_t)blockIdx.z * ((size_t)M * N);

    const __nv_bfloat16* gAhi = Ahi + (size_t)bm * Kld + kOff;
    const __nv_bfloat16* gAlo = Alo + (size_t)bm * Kld + kOff;
    const __nv_bfloat16* gBhi = Bhi + (size_t)bn * Kld + kOff;
    const __nv_bfloat16* gBlo = (MODE == 1) ? (Blo + (size_t)bn * Kld + kOff) : (const __nv_bfloat16*)0;

    const unsigned uAhi = (unsigned)__cvta_generic_to_shared(sAhi);
    const unsigned uAlo = (unsigned)__cvta_generic_to_shared(sAlo);
    const unsigned uBhi = (unsigned)__cvta_generic_to_shared(sBhi);
    const unsigned uBlo = (MODE == 1) ? (unsigned)__cvta_generic_to_shared(sBlo) : 0u;

    const int lrow = t >> 2;
    const int lcol = (t & 3) << 3;

    float acc[2][8][4];
#pragma unroll
    for (int i = 0; i < 2; i++)
#pragma unroll
        for (int j = 0; j < 8; j++)
#pragma unroll
            for (int p = 0; p < 4; p++) acc[i][j][p] = 0.f;

    const int NS = kLen >> 5;

    {
#pragma unroll
        for (int h = 0; h < 2; h++) {
            int row = lrow + (h << 6);
            size_t go = (size_t)row * Kld + lcol;
            unsigned so = ((unsigned)(row * 40 + lcol) << 1);
            CP16(uAhi + so, gAhi + go);
            CP16(uAlo + so, gAlo + go);
            CP16(uBhi + so, gBhi + go);
            if (MODE == 1) CP16(uBlo + so, gBlo + go);
        }
        CPCOMMIT();
    }

    for (int s = 0; s < NS; s++) {
        if (s + 1 < NS) {
            int k0 = (s + 1) << 5, buf = (s + 1) & 1;
#pragma unroll
            for (int h = 0; h < 2; h++) {
                int row = lrow + (h << 6);
                size_t go = (size_t)row * Kld + k0 + lcol;
                unsigned so = ((unsigned)(row * 40 + lcol) << 1) + (unsigned)buf * (SZ << 1);
                CP16(uAhi + so, gAhi + go);
                CP16(uAlo + so, gAlo + go);
                CP16(uBhi + so, gBhi + go);
                if (MODE == 1) CP16(uBlo + so, gBlo + go);
            }
        }
        CPCOMMIT();
        CPWAIT1();
        __syncthreads();

        unsigned bufOff = (unsigned)(s & 1) * (SZ << 1);
#pragma unroll
        for (int kk = 0; kk < 32; kk += 16) {
            uint32_t ah[2][4], al[2][4], bh[4][4], bl[4][4];
#pragma unroll
            for (int mt = 0; mt < 2; mt++) {
                unsigned ra = ((unsigned)((warpM + (mt << 4) + (lane & 15)) * 40 + kk + ((lane >> 4) << 3)) << 1) + bufOff;
                LDSM4(ah[mt], uAhi + ra);
                LDSM4(al[mt], uAlo + ra);
            }
#pragma unroll
            for (int bj = 0; bj < 4; bj++) {
                unsigned rb = ((unsigned)((warpN + (bj << 4) + ((lane >> 4) << 3) + (lane & 7)) * 40 + kk + (((lane >> 3) & 1) << 3)) << 1) + bufOff;
                LDSM4(bh[bj], uBhi + rb);
                if (MODE == 1) LDSM4(bl[bj], uBlo + rb);
            }
#pragma unroll
            for (int mt = 0; mt < 2; mt++)
#pragma unroll
                for (int nt = 0; nt < 8; nt++) {
                    uint32_t b0 = bh[nt >> 1][(nt & 1) << 1];
                    uint32_t b1 = bh[nt >> 1][((nt & 1) << 1) + 1];
                    MMA16816(acc[mt][nt], ah[mt], b0, b1);
                    MMA16816(acc[mt][nt], al[mt], b0, b1);
                    if (MODE == 1) {
                        uint32_t c0 = bl[nt >> 1][(nt & 1) << 1];
                        uint32_t c1 = bl[nt >> 1][((nt & 1) << 1) + 1];
                        MMA16816(acc[mt][nt], ah[mt], c0, c1);
                    }
                }
        }
        __syncthreads();
    }

    float sc = TERN ? g_scale[scaleIdx] : 1.f;
#pragma unroll
    for (int mt = 0; mt < 2; mt++)
#pragma unroll
        for (int nt = 0; nt < 8; nt++) {
            int row = bm + warpM + (mt << 4) + (lane >> 2);
            int col = bn + warpN + (nt << 3) + ((lane & 3) << 1);
#pragma unroll
            for (int half = 0; half < 2; half++) {
                int r = row + half * 8;
                float v0 = acc[mt][nt][half * 2 + 0];
                float v1 = acc[mt][nt][half * 2 + 1];
                if (TERN) { v0 *= sc; v1 *= sc; }
                if (bias) { v0 += bias[col]; v1 += bias[col + 1]; }
                if (res)  { v0 += res[(size_t)r * N + col]; v1 += res[(size_t)r * N + col + 1]; }
                if (RELU) { v0 = fmaxf(v0, 0.f); v1 = fmaxf(v1, 0.f); }
                if (OUT_HILO) {
                    __nv_bfloat16 h0 = __float2bfloat16(v0);
                    __nv_bfloat16 h1 = __float2bfloat16(v1);
                    Chi[(size_t)r * N + col]     = h0;
                    Chi[(size_t)r * N + col + 1] = h1;
                    Clo[(size_t)r * N + col]     = __float2bfloat16(v0 - __bfloat162float(h0));
                    Clo[(size_t)r * N + col + 1] = __float2bfloat16(v1 - __bfloat162float(h1));
                } else {
                    C[(size_t)r * N + col]     = v0;
                    C[(size_t)r * N + col + 1] = v1;
                }
            }
        }
}

// ---------------- fused split-K reduce + residual + LayerNorm (+hi/lo out, in-place x) ----------------
__global__ void ln_red(const float* __restrict__ bias, float* __restrict__ x,
                       __nv_bfloat16* __restrict__ ohi, __nv_bfloat16* __restrict__ olo,
                       const float* __restrict__ gamma, const float* __restrict__ beta)
{
    __shared__ float sred[256];
    const int row = blockIdx.x, t = threadIdx.x;
    const size_t off = (size_t)row * DD;
    float4 p0 = ((const float4*)(g_psum + off))[t];
    float4 p1 = ((const float4*)(g_psum + MMDD + off))[t];
    float4 p2 = ((const float4*)(g_psum + 2 * MMDD + off))[t];
    float4 p3 = ((const float4*)(g_psum + 3 * MMDD + off))[t];
    float4 bb = ((const float4*)bias)[t];
    float4 rr = ((const float4*)(x + off))[t];
    float4 v;
    v.x = ((p0.x + p1.x) + (p2.x + p3.x)) + bb.x + rr.x;
    v.y = ((p0.y + p1.y) + (p2.y + p3.y)) + bb.y + rr.y;
    v.z = ((p0.z + p1.z) + (p2.z + p3.z)) + bb.z + rr.z;
    v.w = ((p0.w + p1.w) + (p2.w + p3.w)) + bb.w + rr.w;

    sred[t] = v.x + v.y + v.z + v.w;
    __syncthreads();
#pragma unroll
    for (int o = 128; o > 0; o >>= 1) { if (t < o) sred[t] += sred[t + o]; __syncthreads(); }
    float mean = sred[0] * (1.f / 1024.f);
    __syncthreads();
    float dx = v.x - mean, dy = v.y - mean, dz = v.z - mean, dw = v.w - mean;
    sred[t] = dx * dx + dy * dy + dz * dz + dw * dw;
    __syncthreads();
#pragma unroll
    for (int o = 128; o > 0; o >>= 1) { if (t < o) sred[t] += sred[t + o]; __syncthreads(); }
    float rstd = rsqrtf(sred[0] * (1.f / 1024.f) + EPSLN);
    float4 g = ((const float4*)gamma)[t];
    float4 b = ((const float4*)beta)[t];
    float4 o4;
    o4.x = dx * rstd * g.x + b.x;
    o4.y = dy * rstd * g.y + b.y;
    o4.z = dz * rstd * g.z + b.z;
    o4.w = dw * rstd * g.w + b.w;
    ((float4*)(x + off))[t] = o4;
    ushort4 h, l;
    __nv_bfloat16 hb;
    hb = __float2bfloat16(o4.x); h.x = __bfloat16_as_ushort(hb); l.x = bf16bits(o4.x - __bfloat162float(hb));
    hb = __float2bfloat16(o4.y); h.y = __bfloat16_as_ushort(hb); l.y = bf16bits(o4.y - __bfloat162float(hb));
    hb = __float2bfloat16(o4.z); h.z = __bfloat16_as_ushort(hb); l.z = bf16bits(o4.z - __bfloat162float(hb));
    hb = __float2bfloat16(o4.w); h.w = __bfloat16_as_ushort(hb); l.w = bf16bits(o4.w - __bfloat162float(hb));
    ((ushort4*)(ohi + off))[t] = h;
    ((ushort4*)(olo + off))[t] = l;
}

// ---------------- plain LayerNorm (+hi/lo out) ----------------
__global__ void ln_kernel(const float* __restrict__ in, float* __restrict__ out,
                          __nv_bfloat16* __restrict__ ohi, __nv_bfloat16* __restrict__ olo,
                          const float* __restrict__ gamma, const float* __restrict__ beta)
{
    __shared__ float sred[256];
    const int row = blockIdx.x, t = threadIdx.x;
    const float4 v = ((const float4*)(in + (size_t)row * DD))[t];
    sred[t] = v.x + v.y + v.z + v.w;
    __syncthreads();
#pragma unroll
    for (int o = 128; o > 0; o >>= 1) { if (t < o) sred[t] += sred[t + o]; __syncthreads(); }
    float mean = sred[0] * (1.f / 1024.f);
    __syncthreads();
    float dx = v.x - mean, dy = v.y - mean, dz = v.z - mean, dw = v.w - mean;
    sred[t] = dx * dx + dy * dy + dz * dz + dw * dw;
    __syncthreads();
#pragma unroll
    for (int o = 128; o > 0; o >>= 1) { if (t < o) sred[t] += sred[t + o]; __syncthreads(); }
    float rstd = rsqrtf(sred[0] * (1.f / 1024.f) + EPSLN);
    float4 g = ((const float4*)gamma)[t];
    float4 b = ((const float4*)beta)[t];
    float4 o4;
    o4.x = dx * rstd * g.x + b.x;
    o4.y = dy * rstd * g.y + b.y;
    o4.z = dz * rstd * g.z + b.z;
    o4.w = dw * rstd * g.w + b.w;
    ((float4*)(out + (size_t)row * DD))[t] = o4;
    ushort4 h, l;
    __nv_bfloat16 hb;
    hb = __float2bfloat16(o4.x); h.x = __bfloat16_as_ushort(hb); l.x = bf16bits(o4.x - __bfloat162float(hb));
    hb = __float2bfloat16(o4.y); h.y = __bfloat16_as_ushort(hb); l.y = bf16bits(o4.y - __bfloat162float(hb));
    hb = __float2bfloat16(o4.z); h.z = __bfloat16_as_ushort(hb); l.z = bf16bits(o4.z - __bfloat162float(hb));
    hb = __float2bfloat16(o4.w); h.w = __bfloat16_as_ushort(hb); l.w = bf16bits(o4.w - __bfloat162float(hb));
    ((ushort4*)(ohi + (size_t)row * DD))[t] = h;
    ((ushort4*)(olo + (size_t)row * DD))[t] = l;
}

// ---------------- grid barrier: monotonic phase, volatile-load polling ----------------
__device__ __forceinline__ void gbar(unsigned k) {
    __syncthreads();
    if (threadIdx.x == 0) {
        __threadfence();
        unsigned tick = atomicAdd(&g_bar_cnt, 1u);
        if (tick == GRU_CTAS - 1) {
            g_bar_cnt = 0;
            __threadfence();
            atomicExch(&g_bar_phase, k);
        } else {
            while (*((volatile unsigned*)&g_bar_phase) < k) { }
            __threadfence();
        }
    }
    __syncthreads();
}

// ---------------- persistent GRU: Whh slice in registers, f32x2 matvec ----------------
__global__ __launch_bounds__(192, 1) void gru_kernel(
    const float* __restrict__ gi, const float* __restrict__ whh,
    const float* __restrict__ bhh, float* __restrict__ x,
    __nv_bfloat16* __restrict__ xhi, __nv_bfloat16* __restrict__ xlo)
{
    __shared__ float hs[2048];     // interleaved: hs[2*d+b]
    __shared__ float sgh[48];
    __shared__ float sbh[24];
    const int tid = threadIdx.x;
    const int base = blockIdx.x * 8;
    const int r = tid >> 3, j = tid & 7;        // r: 0..23 (gate*8+dim), j: k-chunk
    const int gg = r >> 3, ddim = r & 7;

    // preload this thread's Whh row slice into registers (32 float4 = 128 regs)
    float4 wreg[32];
    const float* wrow = whh + (size_t)(gg * 1024 + base + ddim) * 1024;
#pragma unroll
    for (int i = 0; i < 32; i++)
        wreg[i] = *(const float4*)(wrow + (i * 8 + j) * 4);

    if (tid < 24) sbh[tid] = bhh[(tid >> 3) * 1024 + base + (tid & 7)];
    if (tid < 16) {
        int b = tid & 1, d0 = base + (tid >> 1);
        g_h[0][2 * d0 + b] = 0.f;
    }
    gbar(1);

    for (int s = 0; s < SS; s++) {
        const int rb = s & 1, wb = rb ^ 1;

        // prefetch gi for this step (hides L2/DRAM latency behind matvec)
        float ir = 0.f, iz = 0.f, inn = 0.f;
        if (tid < 16) {
            int b = tid & 1, d0 = tid >> 1;
            int dg = base + d0;
            const float* gim = gi + ((size_t)b * SS + s) * 3072;
            ir  = __ldcg(gim + dg);
            iz  = __ldcg(gim + 1024 + dg);
            inn = __ldcg(gim + 2048 + dg);
        }

        for (int idx = tid; idx < 512; idx += 192)
            ((float4*)hs)[idx] = __ldcg((const float4*)&g_h[rb][0] + idx);
        __syncthreads();

        unsigned long long acc = 0ull;
#pragma unroll
        for (int i = 0; i < 32; i++) {
            int c4 = i * 8 + j;
            float4 hA = ((const float4*)hs)[c4 * 2];      // (b0[d],b1[d],b0[d+1],b1[d+1])
            float4 hB = ((const float4*)hs)[c4 * 2 + 1];
            float4 w = wreg[i];
            ffma2(acc, pk2(w.x, w.x), pk2(hA.x, hA.y));
            ffma2(acc, pk2(w.y, w.y), pk2(hA.z, hA.w));
            ffma2(acc, pk2(w.z, w.z), pk2(hB.x, hB.y));
            ffma2(acc, pk2(w.w, w.w), pk2(hB.z, hB.w));
        }
        float2 a2 = unpk(acc);
        float acc0 = a2.x, acc1 = a2.y;
#pragma unroll
        for (int o = 4; o; o >>= 1) {
            acc0 += __shfl_down_sync(0xffffffffu, acc0, o);
            acc1 += __shfl_down_sync(0xffffffffu, acc1, o);
        }
        if (j == 0) { sgh[r * 2] = acc0 + sbh[r]; sgh[r * 2 + 1] = acc1 + sbh[r]; }
        __syncthreads();

        if (tid < 16) {
            int b = tid & 1, d0 = tid >> 1;
            int dg = base + d0;
            float hr = sgh[d0 * 2 + b], hz = sgh[(8 + d0) * 2 + b], hn = sgh[(16 + d0) * 2 + b];
            float rg = 1.f / (1.f + expf(-(ir + hr)));
            float zg = 1.f / (1.f + expf(-(iz + hz)));
            float ng = tanhf(inn + rg * hn);
            float hp = hs[2 * dg + b];
            float hv = (1.f - zg) * ng + zg * hp;
            __stcg(&g_h[wb][2 * dg + b], hv);
            size_t m = (size_t)b * SS + s;
            x[m * 1024 + dg] = hv;
            __nv_bfloat16 hb16 = __float2bfloat16(hv);
            xhi[m * 1024 + dg] = hb16;
            xlo[m * 1024 + dg] = __float2bfloat16(hv - __bfloat162float(hb16));
        }
        gbar(2 + s);
    }

    // reset barrier state for the next graph replay (safe: all CTAs past final barrier)
    if (tid == 0) {
        __threadfence();
        atomicAdd(&g_ack, 1u);
        if (blockIdx.x == 0) {
            while (*((volatile unsigned*)&g_ack) < GRU_CTAS) { }
            g_ack = 0;
            g_bar_phase = 0;
            __threadfence();
        }
    }
}

// ---------------- launch ----------------
extern "C" void kernel_launch(void* const* d_in, const int* in_sizes, int n_in,
                              void* d_out, int out_size) {
    const int*   ids     = (const int*)  d_in[0];
    const float* emb     = (const float*)d_in[1];
    const float* pos     = (const float*)d_in[2];
    const float* gru_wih = (const float*)d_in[3];
    const float* gru_whh = (const float*)d_in[4];
    const float* gru_bih = (const float*)d_in[5];
    const float* gru_bhh = (const float*)d_in[6];
    const float* syn_w   = (const float*)d_in[7];
    const float* syn_b   = (const float*)d_in[8];
    const float* out_w   = (const float*)d_in[9];
    const float* out_b   = (const float*)d_in[10];
    const float* ln_g    = (const float*)d_in[11];
    const float* ln_b    = (const float*)d_in[12];
    const float* on_g    = (const float*)d_in[13];
    const float* on_b    = (const float*)d_in[14];
    const float* head_w  = (const float*)d_in[15];
    const float* head_b  = (const float*)d_in[16];
    float* logits = (float*)d_out;

    float *xg, *yg, *gig, *psg;
    __nv_bfloat16 *qhead, *qsyn, *qout, *wihhi, *wihlo, *xhi, *xlo, *yhi, *ylo, *hhi, *hlo;
    cudaGetSymbolAddress((void**)&xg,   g_x);
    cudaGetSymbolAddress((void**)&yg,   g_y);
    cudaGetSymbolAddress((void**)&gig,  g_gi);
    cudaGetSymbolAddress((void**)&psg,  g_psum);
    cudaGetSymbolAddress((void**)&qhead, g_qhead);
    cudaGetSymbolAddress((void**)&qsyn,  g_qsyn);
    cudaGetSymbolAddress((void**)&qout,  g_qout);
    cudaGetSymbolAddress((void**)&wihhi, g_wihhi);
    cudaGetSymbolAddress((void**)&wihlo, g_wihlo);
    cudaGetSymbolAddress((void**)&xhi, g_xhi);
    cudaGetSymbolAddress((void**)&xlo, g_xlo);
    cudaGetSymbolAddress((void**)&yhi, g_yhi);
    cudaGetSymbolAddress((void**)&ylo, g_ylo);
    cudaGetSymbolAddress((void**)&hhi, g_hhi);
    cudaGetSymbolAddress((void**)&hlo, g_hlo);

    static bool attr_done = false;
    if (!attr_done) {
        cudaFuncSetAttribute(bgemm<1, false, false, false>, cudaFuncAttributeMaxDynamicSharedMemorySize, 81920);
        cudaFuncSetAttribute(bgemm<0, true, true,  true >, cudaFuncAttributeMaxDynamicSharedMemorySize, 61440);
        cudaFuncSetAttribute(bgemm<0, true, false, false>, cudaFuncAttributeMaxDynamicSharedMemorySize, 61440);
        attr_done = true;
    }

    // 1) abs-mean scales
    long nVD4 = (long)VV * DD / 4, nND4 = (long)NNH * DD / 4;
    absmean_part<<<512, 256>>>((const float4*)emb,    nVD4, 0);
    absmean_part<<<512, 256>>>((const float4*)head_w, nVD4, 1);
    for (int l = 0; l < 4; l++) {
        absmean_part<<<512, 256>>>((const float4*)(syn_w + (size_t)l * NNH * DD), nND4, 2 + l);
        absmean_part<<<512, 256>>>((const float4*)(out_w + (size_t)l * DD * NNH), nND4, 6 + l);
    }
    absmean_final<<<10, 256>>>();

    // 2) quantize weights
    tern_quant<<<(int)(nVD4 / 256), 256>>>((const float4*)head_w, (ushort4*)qhead, 1, (int)nVD4);
    for (int l = 0; l < 4; l++) {
        tern_quant<<<(int)(nND4 / 256), 256>>>((const float4*)(syn_w + (size_t)l * NNH * DD),
                                               (ushort4*)(qsyn + (size_t)l * NNH * DD), 2 + l, (int)nND4);
        tern_quant<<<(int)(nND4 / 256), 256>>>((const float4*)(out_w + (size_t)l * DD * NNH),
                                               (ushort4*)(qout + (size_t)l * DD * NNH), 6 + l, (int)nND4);
    }
    int n4wih = 3 * DD * DD / 4;
    hilo_quant<<<n4wih / 256, 256>>>((const float4*)gru_wih, (ushort4*)wihhi, (ushort4*)wihlo, n4wih);

    // 3) embedding (+ hi/lo)
    embed_kernel<<<4096, 256>>>(ids, emb, pos, xg, xhi, xlo);

    // 4) GRU input projections
    bgemm<1, false, false, false><<<dim3(3072 / 128, MROWS / 128, 1), 256, 81920>>>(
        xhi, xlo, wihhi, wihlo, gig, (__nv_bfloat16*)0, (__nv_bfloat16*)0,
        gru_bih, (const float*)0, MROWS, 3072, DD, DD, 0);

    // 5) GRU recurrence (persistent; writes x + hi/lo directly)
    gru_kernel<<<GRU_CTAS, 192>>>(gig, gru_whh, gru_bhh, xg, xhi, xlo);

    // 6) MLP layers
    for (int l = 0; l < 4; l++) {
        bgemm<0, true, true, true><<<dim3(NNH / 128, MROWS / 128, 1), 256, 61440>>>(
            xhi, xlo, qsyn + (size_t)l * NNH * DD, (const __nv_bfloat16*)0,
            (float*)0, hhi, hlo, syn_b + (size_t)l * NNH, (const float*)0,
            MROWS, NNH, DD, DD, 2 + l);
        bgemm<0, true, false, false><<<dim3(DD / 128, MROWS / 128, 4), 256, 61440>>>(
            hhi, hlo, qout + (size_t)l * DD * NNH, (const __nv_bfloat16*)0,
            psg, (__nv_bfloat16*)0, (__nv_bfloat16*)0, (const float*)0, (const float*)0,
            MROWS, DD, NNH, NNH / 4, 6 + l);
        ln_red<<<MROWS, 256>>>(out_b + (size_t)l * DD, xg, xhi, xlo,
                               ln_g + (size_t)l * DD, ln_b + (size_t)l * DD);
    }

    // 7) final LN + head
    ln_kernel<<<MROWS, 256>>>(xg, yg, yhi, ylo, on_g, on_b);
    bgemm<0, true, false, false><<<dim3(VV / 128, MROWS / 128, 1), 256, 61440>>>(
        yhi, ylo, qhead, (const __nv_bfloat16*)0,
        logits, (__nv_bfloat16*)0, (__nv_bfloat16*)0, head_b, (const float*)0,
        MROWS, VV, DD, DD, 1);
}

// round 5
// speedup vs baseline: 1.5110x; 1.0097x over previous
#include <cuda_runtime.h>
#include <cuda_bf16.h>
#include <math.h>
#include <stdint.h>
#include <stddef.h>

#define SS 512
#define DD 1024
#define NNH 4096
#define VV 32000
#define MROWS 1024
#define MMDD (MROWS * DD)
#define EPSLN 1e-5f
#define GRU_CTAS 128

// ---------------- device scratch ----------------
__device__ float  g_x[MROWS * DD];
__device__ float  g_y[MROWS * DD];
__device__ float  g_gi[MROWS * 3 * DD];
__device__ float  g_psum[4 * MROWS * DD];
__device__ float  g_h[2][2 * DD];
__device__ double g_part[10 * 512];
__device__ float  g_scale[10];
__device__ float  g_scaleinv[10];
__device__ unsigned g_bar_cnt;
__device__ unsigned g_bar_phase;
__device__ unsigned g_ack;

// bf16 buffers
__device__ __nv_bfloat16 g_qhead[VV * DD];
__device__ __nv_bfloat16 g_qsyn[4 * NNH * DD];
__device__ __nv_bfloat16 g_qout[4 * NNH * DD];
__device__ __nv_bfloat16 g_wihhi[3 * DD * DD];
__device__ __nv_bfloat16 g_wihlo[3 * DD * DD];
__device__ __nv_bfloat16 g_xhi[MROWS * DD],  g_xlo[MROWS * DD];
__device__ __nv_bfloat16 g_yhi[MROWS * DD],  g_ylo[MROWS * DD];
__device__ __nv_bfloat16 g_hhi[MROWS * NNH], g_hlo[MROWS * NNH];

// ---------------- asm helpers ----------------
#define CP16(dst, src) asm volatile("cp.async.cg.shared.global [%0], [%1], 16;" :: "r"(dst), "l"(src))
#define CPCOMMIT() asm volatile("cp.async.commit_group;")
#define CPWAIT1()  asm volatile("cp.async.wait_group 1;")
#define LDSM4(r, addr) asm volatile( \
    "ldmatrix.sync.aligned.m8n8.x4.shared.b16 {%0,%1,%2,%3}, [%4];" \
    : "=r"((r)[0]), "=r"((r)[1]), "=r"((r)[2]), "=r"((r)[3]) : "r"(addr))
#define MMA16816(d, a, b0, b1) asm volatile( \
    "mma.sync.aligned.m16n8k16.row.col.f32.bf16.bf16.f32 " \
    "{%0,%1,%2,%3},{%4,%5,%6,%7},{%8,%9},{%0,%1,%2,%3};" \
    : "+f"((d)[0]), "+f"((d)[1]), "+f"((d)[2]), "+f"((d)[3]) \
    : "r"((a)[0]), "r"((a)[1]), "r"((a)[2]), "r"((a)[3]), "r"(b0), "r"(b1))

__device__ __forceinline__ unsigned short bf16bits(float x) {
    return __bfloat16_as_ushort(__float2bfloat16(x));
}
__device__ __forceinline__ unsigned long long pk2(float x, float y) {
    unsigned long long r;
    asm("mov.b64 %0, {%1, %2};" : "=l"(r) : "f"(x), "f"(y));
    return r;
}
__device__ __forceinline__ void ffma2(unsigned long long& d, unsigned long long a, unsigned long long b) {
    asm("fma.rn.f32x2 %0, %1, %2, %0;" : "+l"(d) : "l"(a), "l"(b));
}
__device__ __forceinline__ float2 unpk(unsigned long long v) {
    float2 f;
    asm("mov.b64 {%0, %1}, %2;" : "=f"(f.x), "=f"(f.y) : "l"(v));
    return f;
}

// ---------------- abs-mean scale: 8 independent chains ----------------
__global__ __launch_bounds__(256, 2) void absmean_part(const float4* __restrict__ src, long n4, int slot) {
    __shared__ double sred[256];
    double a[8];
#pragma unroll
    for (int c = 0; c < 8; c++) a[c] = 0.0;
    const long stride = (long)gridDim.x * 256;
    long i = (long)blockIdx.x * 256 + threadIdx.x;
    for (; i + 7 * stride < n4; i += 8 * stride) {
        float4 v[8];
#pragma unroll
        for (int c = 0; c < 8; c++) v[c] = src[i + c * stride];
#pragma unroll
        for (int c = 0; c < 8; c++)
            a[c] += (double)(fabsf(v[c].x) + fabsf(v[c].y)) + (double)(fabsf(v[c].z) + fabsf(v[c].w));
    }
    for (; i < n4; i += stride) {
        float4 v = src[i];
        a[0] += (double)(fabsf(v.x) + fabsf(v.y)) + (double)(fabsf(v.z) + fabsf(v.w));
    }
    sred[threadIdx.x] = ((a[0] + a[1]) + (a[2] + a[3])) + ((a[4] + a[5]) + (a[6] + a[7]));
    __syncthreads();
#pragma unroll
    for (int o = 128; o > 0; o >>= 1) {
        if ((int)threadIdx.x < o) sred[threadIdx.x] += sred[threadIdx.x + o];
        __syncthreads();
    }
    if (threadIdx.x == 0) g_part[slot * 512 + blockIdx.x] = sred[0];
}

// finalize a contiguous range of slots: slot = base + blockIdx.x
__global__ void absmean_final(int base) {
    __shared__ double sred[256];
    int slot = base + blockIdx.x, t = threadIdx.x;
    sred[t] = g_part[slot * 512 + t] + g_part[slot * 512 + 256 + t];
    __syncthreads();
#pragma unroll
    for (int o = 128; o > 0; o >>= 1) {
        if (t < o) sred[t] += sred[t + o];
        __syncthreads();
    }
    if (t == 0) {
        double cnt = (slot < 2) ? (double)VV * DD : (double)NNH * DD;
        double s = sred[0] / cnt + 1e-8;
        g_scale[slot]    = (float)s;
        g_scaleinv[slot] = (float)(1.0 / s);
    }
}

// ---------------- weight quantization ----------------
__global__ void tern_quant(const float4* __restrict__ w, ushort4* __restrict__ q,
                           int slot, int n4) {
    int i = blockIdx.x * 256 + threadIdx.x;
    if (i >= n4) return;
    float inv = g_scaleinv[slot];
    float4 v = w[i];
    ushort4 o;
    o.x = bf16bits(rintf(fminf(fmaxf(v.x * inv, -1.f), 1.f)));
    o.y = bf16bits(rintf(fminf(fmaxf(v.y * inv, -1.f), 1.f)));
    o.z = bf16bits(rintf(fminf(fmaxf(v.z * inv, -1.f), 1.f)));
    o.w = bf16bits(rintf(fminf(fmaxf(v.w * inv, -1.f), 1.f)));
    q[i] = o;
}

__global__ void hilo_quant(const float4* __restrict__ w, ushort4* __restrict__ hi,
                           ushort4* __restrict__ lo, int n4) {
    int i = blockIdx.x * 256 + threadIdx.x;
    if (i >= n4) return;
    float4 v = w[i];
    ushort4 h, l;
    __nv_bfloat16 hb;
    hb = __float2bfloat16(v.x); h.x = __bfloat16_as_ushort(hb); l.x = bf16bits(v.x - __bfloat162float(hb));
    hb = __float2bfloat16(v.y); h.y = __bfloat16_as_ushort(hb); l.y = bf16bits(v.y - __bfloat162float(hb));
    hb = __float2bfloat16(v.z); h.z = __bfloat16_as_ushort(hb); l.z = bf16bits(v.z - __bfloat162float(hb));
    hb = __float2bfloat16(v.w); h.w = __bfloat16_as_ushort(hb); l.w = bf16bits(v.w - __bfloat162float(hb));
    hi[i] = h; lo[i] = l;
}

// ---------------- embedding ----------------
__global__ void embed_kernel(const int* __restrict__ ids, const float* __restrict__ emb,
                             const float* __restrict__ pos, float* __restrict__ x,
                             __nv_bfloat16* __restrict__ xhi, __nv_bfloat16* __restrict__ xlo) {
    int i = blockIdx.x * 256 + threadIdx.x;
    int d = i & (DD - 1);
    int s = (i >> 10) & (SS - 1);
    int b = i >> 19;
    int tok = ids[b * SS + s];
    float w = emb[(size_t)tok * DD + d];
    float tn = g_scale[0] * rintf(fminf(fmaxf(w * g_scaleinv[0], -1.f), 1.f));
    float v = tn + pos[s * DD + d];
    x[i] = v;
    __nv_bfloat16 h = __float2bfloat16(v);
    xhi[i] = h;
    xlo[i] = __float2bfloat16(v - __bfloat162float(h));
}

// ---------------- bf16 tensor-core GEMM NT ----------------
template<int MODE, bool TERN, bool RELU, bool OUT_HILO>
__global__ __launch_bounds__(256) void bgemm(
    const __nv_bfloat16* __restrict__ Ahi, const __nv_bfloat16* __restrict__ Alo,
    const __nv_bfloat16* __restrict__ Bhi, const __nv_bfloat16* __restrict__ Blo,
    float* __restrict__ C, __nv_bfloat16* __restrict__ Chi, __nv_bfloat16* __restrict__ Clo,
    const float* __restrict__ bias, const float* __restrict__ res,
    int M, int N, int Kld, int kLen, int scaleIdx)
{
    constexpr int SZ = 128 * 40;
    extern __shared__ __align__(16) __nv_bfloat16 smb[];
    __nv_bfloat16* sAhi = smb;
    __nv_bfloat16* sAlo = smb + 2 * SZ;
    __nv_bfloat16* sBhi = smb + 4 * SZ;
    __nv_bfloat16* sBlo = smb + 6 * SZ;

    const int t = threadIdx.x;
    const int lane = t & 31;
    const int w = t >> 5;
    const int warpM = (w >> 1) << 5;
    const int warpN = (w & 1) << 6;
    const int bm = blockIdx.y << 7, bn = blockIdx.x << 7;
    const int kOff = blockIdx.z * kLen;
    if (gridDim.z > 1) C += (size_t)blockIdx.z * ((size_t)M * N);

    const __nv_bfloat16* gAhi = Ahi + (size_t)bm * Kld + kOff;
    const __nv_bfloat16* gAlo = Alo + (size_t)bm * Kld + kOff;
    const __nv_bfloat16* gBhi = Bhi + (size_t)bn * Kld + kOff;
    const __nv_bfloat16* gBlo = (MODE == 1) ? (Blo + (size_t)bn * Kld + kOff) : (const __nv_bfloat16*)0;

    const unsigned uAhi = (unsigned)__cvta_generic_to_shared(sAhi);
    const unsigned uAlo = (unsigned)__cvta_generic_to_shared(sAlo);
    const unsigned uBhi = (unsigned)__cvta_generic_to_shared(sBhi);
    const unsigned uBlo = (MODE == 1) ? (unsigned)__cvta_generic_to_shared(sBlo) : 0u;

    const int lrow = t >> 2;
    const int lcol = (t & 3) << 3;

    float acc[2][8][4];
#pragma unroll
    for (int i = 0; i < 2; i++)
#pragma unroll
        for (int j = 0; j < 8; j++)
#pragma unroll
            for (int p = 0; p < 4; p++) acc[i][j][p] = 0.f;

    const int NS = kLen >> 5;

    {
#pragma unroll
        for (int h = 0; h < 2; h++) {
            int row = lrow + (h << 6);
            size_t go = (size_t)row * Kld + lcol;
            unsigned so = ((unsigned)(row * 40 + lcol) << 1);
            CP16(uAhi + so, gAhi + go);
            CP16(uAlo + so, gAlo + go);
            CP16(uBhi + so, gBhi + go);
            if (MODE == 1) CP16(uBlo + so, gBlo + go);
        }
        CPCOMMIT();
    }

    for (int s = 0; s < NS; s++) {
        if (s + 1 < NS) {
            int k0 = (s + 1) << 5, buf = (s + 1) & 1;
#pragma unroll
            for (int h = 0; h < 2; h++) {
                int row = lrow + (h << 6);
                size_t go = (size_t)row * Kld + k0 + lcol;
                unsigned so = ((unsigned)(row * 40 + lcol) << 1) + (unsigned)buf * (SZ << 1);
                CP16(uAhi + so, gAhi + go);
                CP16(uAlo + so, gAlo + go);
                CP16(uBhi + so, gBhi + go);
                if (MODE == 1) CP16(uBlo + so, gBlo + go);
            }
        }
        CPCOMMIT();
        CPWAIT1();
        __syncthreads();

        unsigned bufOff = (unsigned)(s & 1) * (SZ << 1);
#pragma unroll
        for (int kk = 0; kk < 32; kk += 16) {
            uint32_t ah[2][4], al[2][4], bh[4][4], bl[4][4];
#pragma unroll
            for (int mt = 0; mt < 2; mt++) {
                unsigned ra = ((unsigned)((warpM + (mt << 4) + (lane & 15)) * 40 + kk + ((lane >> 4) << 3)) << 1) + bufOff;
                LDSM4(ah[mt], uAhi + ra);
                LDSM4(al[mt], uAlo + ra);
            }
#pragma unroll
            for (int bj = 0; bj < 4; bj++) {
                unsigned rb = ((unsigned)((warpN + (bj << 4) + ((lane >> 4) << 3) + (lane & 7)) * 40 + kk + (((lane >> 3) & 1) << 3)) << 1) + bufOff;
                LDSM4(bh[bj], uBhi + rb);
                if (MODE == 1) LDSM4(bl[bj], uBlo + rb);
            }
#pragma unroll
            for (int mt = 0; mt < 2; mt++)
#pragma unroll
                for (int nt = 0; nt < 8; nt++) {
                    uint32_t b0 = bh[nt >> 1][(nt & 1) << 1];
                    uint32_t b1 = bh[nt >> 1][((nt & 1) << 1) + 1];
                    MMA16816(acc[mt][nt], ah[mt], b0, b1);
                    MMA16816(acc[mt][nt], al[mt], b0, b1);
                    if (MODE == 1) {
                        uint32_t c0 = bl[nt >> 1][(nt & 1) << 1];
                        uint32_t c1 = bl[nt >> 1][((nt & 1) << 1) + 1];
                        MMA16816(acc[mt][nt], ah[mt], c0, c1);
                    }
                }
        }
        __syncthreads();
    }

    float sc = TERN ? g_scale[scaleIdx] : 1.f;
#pragma unroll
    for (int mt = 0; mt < 2; mt++)
#pragma unroll
        for (int nt = 0; nt < 8; nt++) {
            int row = bm + warpM + (mt << 4) + (lane >> 2);
            int col = bn + warpN + (nt << 3) + ((lane & 3) << 1);
#pragma unroll
            for (int half = 0; half < 2; half++) {
                int r = row + half * 8;
                float v0 = acc[mt][nt][half * 2 + 0];
                float v1 = acc[mt][nt][half * 2 + 1];
                if (TERN) { v0 *= sc; v1 *= sc; }
                if (bias) { v0 += bias[col]; v1 += bias[col + 1]; }
                if (res)  { v0 += res[(size_t)r * N + col]; v1 += res[(size_t)r * N + col + 1]; }
                if (RELU) { v0 = fmaxf(v0, 0.f); v1 = fmaxf(v1, 0.f); }
                if (OUT_HILO) {
                    __nv_bfloat16 h0 = __float2bfloat16(v0);
                    __nv_bfloat16 h1 = __float2bfloat16(v1);
                    Chi[(size_t)r * N + col]     = h0;
                    Chi[(size_t)r * N + col + 1] = h1;
                    Clo[(size_t)r * N + col]     = __float2bfloat16(v0 - __bfloat162float(h0));
                    Clo[(size_t)r * N + col + 1] = __float2bfloat16(v1 - __bfloat162float(h1));
                } else {
                    C[(size_t)r * N + col]     = v0;
                    C[(size_t)r * N + col + 1] = v1;
                }
            }
        }
}

// ---------------- fused split-K reduce + residual + LayerNorm ----------------
__global__ void ln_red(const float* __restrict__ bias, float* __restrict__ x,
                       __nv_bfloat16* __restrict__ ohi, __nv_bfloat16* __restrict__ olo,
                       const float* __restrict__ gamma, const float* __restrict__ beta)
{
    __shared__ float sred[256];
    const int row = blockIdx.x, t = threadIdx.x;
    const size_t off = (size_t)row * DD;
    float4 p0 = ((const float4*)(g_psum + off))[t];
    float4 p1 = ((const float4*)(g_psum + MMDD + off))[t];
    float4 p2 = ((const float4*)(g_psum + 2 * MMDD + off))[t];
    float4 p3 = ((const float4*)(g_psum + 3 * MMDD + off))[t];
    float4 bb = ((const float4*)bias)[t];
    float4 rr = ((const float4*)(x + off))[t];
    float4 v;
    v.x = ((p0.x + p1.x) + (p2.x + p3.x)) + bb.x + rr.x;
    v.y = ((p0.y + p1.y) + (p2.y + p3.y)) + bb.y + rr.y;
    v.z = ((p0.z + p1.z) + (p2.z + p3.z)) + bb.z + rr.z;
    v.w = ((p0.w + p1.w) + (p2.w + p3.w)) + bb.w + rr.w;

    sred[t] = v.x + v.y + v.z + v.w;
    __syncthreads();
#pragma unroll
    for (int o = 128; o > 0; o >>= 1) { if (t < o) sred[t] += sred[t + o]; __syncthreads(); }
    float mean = sred[0] * (1.f / 1024.f);
    __syncthreads();
    float dx = v.x - mean, dy = v.y - mean, dz = v.z - mean, dw = v.w - mean;
    sred[t] = dx * dx + dy * dy + dz * dz + dw * dw;
    __syncthreads();
#pragma unroll
    for (int o = 128; o > 0; o >>= 1) { if (t < o) sred[t] += sred[t + o]; __syncthreads(); }
    float rstd = rsqrtf(sred[0] * (1.f / 1024.f) + EPSLN);
    float4 g = ((const float4*)gamma)[t];
    float4 b = ((const float4*)beta)[t];
    float4 o4;
    o4.x = dx * rstd * g.x + b.x;
    o4.y = dy * rstd * g.y + b.y;
    o4.z = dz * rstd * g.z + b.z;
    o4.w = dw * rstd * g.w + b.w;
    ((float4*)(x + off))[t] = o4;
    ushort4 h, l;
    __nv_bfloat16 hb;
    hb = __float2bfloat16(o4.x); h.x = __bfloat16_as_ushort(hb); l.x = bf16bits(o4.x - __bfloat162float(hb));
    hb = __float2bfloat16(o4.y); h.y = __bfloat16_as_ushort(hb); l.y = bf16bits(o4.y - __bfloat162float(hb));
    hb = __float2bfloat16(o4.z); h.z = __bfloat16_as_ushort(hb); l.z = bf16bits(o4.z - __bfloat162float(hb));
    hb = __float2bfloat16(o4.w); h.w = __bfloat16_as_ushort(hb); l.w = bf16bits(o4.w - __bfloat162float(hb));
    ((ushort4*)(ohi + off))[t] = h;
    ((ushort4*)(olo + off))[t] = l;
}

// ---------------- plain LayerNorm ----------------
__global__ void ln_kernel(const float* __restrict__ in, float* __restrict__ out,
                          __nv_bfloat16* __restrict__ ohi, __nv_bfloat16* __restrict__ olo,
                          const float* __restrict__ gamma, const float* __restrict__ beta)
{
    __shared__ float sred[256];
    const int row = blockIdx.x, t = threadIdx.x;
    const float4 v = ((const float4*)(in + (size_t)row * DD))[t];
    sred[t] = v.x + v.y + v.z + v.w;
    __syncthreads();
#pragma unroll
    for (int o = 128; o > 0; o >>= 1) { if (t < o) sred[t] += sred[t + o]; __syncthreads(); }
    float mean = sred[0] * (1.f / 1024.f);
    __syncthreads();
    float dx = v.x - mean, dy = v.y - mean, dz = v.z - mean, dw = v.w - mean;
    sred[t] = dx * dx + dy * dy + dz * dz + dw * dw;
    __syncthreads();
#pragma unroll
    for (int o = 128; o > 0; o >>= 1) { if (t < o) sred[t] += sred[t + o]; __syncthreads(); }
    float rstd = rsqrtf(sred[0] * (1.f / 1024.f) + EPSLN);
    float4 g = ((const float4*)gamma)[t];
    float4 b = ((const float4*)beta)[t];
    float4 o4;
    o4.x = dx * rstd * g.x + b.x;
    o4.y = dy * rstd * g.y + b.y;
    o4.z = dz * rstd * g.z + b.z;
    o4.w = dw * rstd * g.w + b.w;
    ((float4*)(out + (size_t)row * DD))[t] = o4;
    ushort4 h, l;
    __nv_bfloat16 hb;
    hb = __float2bfloat16(o4.x); h.x = __bfloat16_as_ushort(hb); l.x = bf16bits(o4.x - __bfloat162float(hb));
    hb = __float2bfloat16(o4.y); h.y = __bfloat16_as_ushort(hb); l.y = bf16bits(o4.y - __bfloat162float(hb));
    hb = __float2bfloat16(o4.z); h.z = __bfloat16_as_ushort(hb); l.z = bf16bits(o4.z - __bfloat162float(hb));
    hb = __float2bfloat16(o4.w); h.w = __bfloat16_as_ushort(hb); l.w = bf16bits(o4.w - __bfloat162float(hb));
    ((ushort4*)(ohi + (size_t)row * DD))[t] = h;
    ((ushort4*)(olo + (size_t)row * DD))[t] = l;
}

// ---------------- grid barrier ----------------
__device__ __forceinline__ void gbar(unsigned k) {
    __syncthreads();
    if (threadIdx.x == 0) {
        __threadfence();
        unsigned tick = atomicAdd(&g_bar_cnt, 1u);
        if (tick == GRU_CTAS - 1) {
            g_bar_cnt = 0;
            __threadfence();
            atomicExch(&g_bar_phase, k);
        } else {
            while (*((volatile unsigned*)&g_bar_phase) < k) { }
            __threadfence();
        }
    }
    __syncthreads();
}

// ---------------- persistent GRU ----------------
__global__ __launch_bounds__(192, 1) void gru_kernel(
    const float* __restrict__ gi, const float* __restrict__ whh,
    const float* __restrict__ bhh, float* __restrict__ x,
    __nv_bfloat16* __restrict__ xhi, __nv_bfloat16* __restrict__ xlo)
{
    __shared__ float hs[2048];
    __shared__ float sgh[48];
    __shared__ float sbh[24];
    const int tid = threadIdx.x;
    const int base = blockIdx.x * 8;
    const int r = tid >> 3, j = tid & 7;
    const int gg = r >> 3, ddim = r & 7;

    float4 wreg[32];
    const float* wrow = whh + (size_t)(gg * 1024 + base + ddim) * 1024;
#pragma unroll
    for (int i = 0; i < 32; i++)
        wreg[i] = *(const float4*)(wrow + (i * 8 + j) * 4);

    if (tid < 24) sbh[tid] = bhh[(tid >> 3) * 1024 + base + (tid & 7)];
    if (tid < 16) {
        int b = tid & 1, d0 = base + (tid >> 1);
        g_h[0][2 * d0 + b] = 0.f;
    }
    gbar(1);

    for (int s = 0; s < SS; s++) {
        const int rb = s & 1, wb = rb ^ 1;

        float ir = 0.f, iz = 0.f, inn = 0.f;
        if (tid < 16) {
            int b = tid & 1, d0 = tid >> 1;
            int dg = base + d0;
            const float* gim = gi + ((size_t)b * SS + s) * 3072;
            ir  = __ldcg(gim + dg);
            iz  = __ldcg(gim + 1024 + dg);
            inn = __ldcg(gim + 2048 + dg);
        }

        for (int idx = tid; idx < 512; idx += 192)
            ((float4*)hs)[idx] = __ldcg((const float4*)&g_h[rb][0] + idx);
        __syncthreads();

        unsigned long long acc = 0ull;
#pragma unroll
        for (int i = 0; i < 32; i++) {
            int c4 = i * 8 + j;
            float4 hA = ((const float4*)hs)[c4 * 2];
            float4 hB = ((const float4*)hs)[c4 * 2 + 1];
            float4 w = wreg[i];
            ffma2(acc, pk2(w.x, w.x), pk2(hA.x, hA.y));
            ffma2(acc, pk2(w.y, w.y), pk2(hA.z, hA.w));
            ffma2(acc, pk2(w.z, w.z), pk2(hB.x, hB.y));
            ffma2(acc, pk2(w.w, w.w), pk2(hB.z, hB.w));
        }
        float2 a2 = unpk(acc);
        float acc0 = a2.x, acc1 = a2.y;
#pragma unroll
        for (int o = 4; o; o >>= 1) {
            acc0 += __shfl_down_sync(0xffffffffu, acc0, o);
            acc1 += __shfl_down_sync(0xffffffffu, acc1, o);
        }
        if (j == 0) { sgh[r * 2] = acc0 + sbh[r]; sgh[r * 2 + 1] = acc1 + sbh[r]; }
        __syncthreads();

        if (tid < 16) {
            int b = tid & 1, d0 = tid >> 1;
            int dg = base + d0;
            float hr = sgh[d0 * 2 + b], hz = sgh[(8 + d0) * 2 + b], hn = sgh[(16 + d0) * 2 + b];
            float rg = 1.f / (1.f + expf(-(ir + hr)));
            float zg = 1.f / (1.f + expf(-(iz + hz)));
            float ng = tanhf(inn + rg * hn);
            float hp = hs[2 * dg + b];
            float hv = (1.f - zg) * ng + zg * hp;
            __stcg(&g_h[wb][2 * dg + b], hv);
            size_t m = (size_t)b * SS + s;
            x[m * 1024 + dg] = hv;
            __nv_bfloat16 hb16 = __float2bfloat16(hv);
            xhi[m * 1024 + dg] = hb16;
            xlo[m * 1024 + dg] = __float2bfloat16(hv - __bfloat162float(hb16));
        }
        gbar(2 + s);
    }

    if (tid == 0) {
        __threadfence();
        atomicAdd(&g_ack, 1u);
        if (blockIdx.x == 0) {
            while (*((volatile unsigned*)&g_ack) < GRU_CTAS) { }
            g_ack = 0;
            g_bar_phase = 0;
            __threadfence();
        }
    }
}

// ---------------- launch ----------------
extern "C" void kernel_launch(void* const* d_in, const int* in_sizes, int n_in,
                              void* d_out, int out_size) {
    const int*   ids     = (const int*)  d_in[0];
    const float* emb     = (const float*)d_in[1];
    const float* pos     = (const float*)d_in[2];
    const float* gru_wih = (const float*)d_in[3];
    const float* gru_whh = (const float*)d_in[4];
    const float* gru_bih = (const float*)d_in[5];
    const float* gru_bhh = (const float*)d_in[6];
    const float* syn_w   = (const float*)d_in[7];
    const float* syn_b   = (const float*)d_in[8];
    const float* out_w   = (const float*)d_in[9];
    const float* out_b   = (const float*)d_in[10];
    const float* ln_g    = (const float*)d_in[11];
    const float* ln_b    = (const float*)d_in[12];
    const float* on_g    = (const float*)d_in[13];
    const float* on_b    = (const float*)d_in[14];
    const float* head_w  = (const float*)d_in[15];
    const float* head_b  = (const float*)d_in[16];
    float* logits = (float*)d_out;

    float *xg, *yg, *gig, *psg;
    __nv_bfloat16 *qhead, *qsyn, *qout, *wihhi, *wihlo, *xhi, *xlo, *yhi, *ylo, *hhi, *hlo;
    cudaGetSymbolAddress((void**)&xg,   g_x);
    cudaGetSymbolAddress((void**)&yg,   g_y);
    cudaGetSymbolAddress((void**)&gig,  g_gi);
    cudaGetSymbolAddress((void**)&psg,  g_psum);
    cudaGetSymbolAddress((void**)&qhead, g_qhead);
    cudaGetSymbolAddress((void**)&qsyn,  g_qsyn);
    cudaGetSymbolAddress((void**)&qout,  g_qout);
    cudaGetSymbolAddress((void**)&wihhi, g_wihhi);
    cudaGetSymbolAddress((void**)&wihlo, g_wihlo);
    cudaGetSymbolAddress((void**)&xhi, g_xhi);
    cudaGetSymbolAddress((void**)&xlo, g_xlo);
    cudaGetSymbolAddress((void**)&yhi, g_yhi);
    cudaGetSymbolAddress((void**)&ylo, g_ylo);
    cudaGetSymbolAddress((void**)&hhi, g_hhi);
    cudaGetSymbolAddress((void**)&hlo, g_hlo);

    static cudaStream_t s1, s2;
    static cudaEvent_t evRoot, ev1, ev2;
    static bool init_done = false;
    if (!init_done) {
        cudaFuncSetAttribute(bgemm<1, false, false, false>, cudaFuncAttributeMaxDynamicSharedMemorySize, 81920);
        cudaFuncSetAttribute(bgemm<0, true, true,  true >, cudaFuncAttributeMaxDynamicSharedMemorySize, 61440);
        cudaFuncSetAttribute(bgemm<0, true, false, false>, cudaFuncAttributeMaxDynamicSharedMemorySize, 61440);
        cudaStreamCreateWithFlags(&s1, cudaStreamNonBlocking);
        cudaStreamCreateWithFlags(&s2, cudaStreamNonBlocking);
        cudaEventCreateWithFlags(&evRoot, cudaEventDisableTiming);
        cudaEventCreateWithFlags(&ev1, cudaEventDisableTiming);
        cudaEventCreateWithFlags(&ev2, cudaEventDisableTiming);
        init_done = true;
    }

    long nVD4 = (long)VV * DD / 4, nND4 = (long)NNH * DD / 4;

    // fork side streams off the main (capture) stream
    cudaEventRecord(evRoot, 0);
    cudaStreamWaitEvent(s1, evRoot, 0);
    cudaStreamWaitEvent(s2, evRoot, 0);

    // side stream 1: layer weight scales + quantization (needed after GRU)
    for (int l = 0; l < 4; l++) {
        absmean_part<<<512, 256, 0, s1>>>((const float4*)(syn_w + (size_t)l * NNH * DD), nND4, 2 + l);
        absmean_part<<<512, 256, 0, s1>>>((const float4*)(out_w + (size_t)l * DD * NNH), nND4, 6 + l);
    }
    absmean_final<<<8, 256, 0, s1>>>(2);
    for (int l = 0; l < 4; l++) {
        tern_quant<<<(int)(nND4 / 256), 256, 0, s1>>>((const float4*)(syn_w + (size_t)l * NNH * DD),
                                                      (ushort4*)(qsyn + (size_t)l * NNH * DD), 2 + l, (int)nND4);
        tern_quant<<<(int)(nND4 / 256), 256, 0, s1>>>((const float4*)(out_w + (size_t)l * DD * NNH),
                                                      (ushort4*)(qout + (size_t)l * DD * NNH), 6 + l, (int)nND4);
    }
    cudaEventRecord(ev1, s1);

    // side stream 2: head scale + quantization (needed only at the end)
    absmean_part<<<512, 256, 0, s2>>>((const float4*)head_w, nVD4, 1);
    absmean_final<<<1, 256, 0, s2>>>(1);
    tern_quant<<<(int)(nVD4 / 256), 256, 0, s2>>>((const float4*)head_w, (ushort4*)qhead, 1, (int)nVD4);
    cudaEventRecord(ev2, s2);

    // main stream: emb scale -> embed -> in-proj -> GRU
    int n4wih = 3 * DD * DD / 4;
    hilo_quant<<<n4wih / 256, 256>>>((const float4*)gru_wih, (ushort4*)wihhi, (ushort4*)wihlo, n4wih);
    absmean_part<<<512, 256>>>((const float4*)emb, nVD4, 0);
    absmean_final<<<1, 256>>>(0);
    embed_kernel<<<4096, 256>>>(ids, emb, pos, xg, xhi, xlo);
    bgemm<1, false, false, false><<<dim3(3072 / 128, MROWS / 128, 1), 256, 81920>>>(
        xhi, xlo, wihhi, wihlo, gig, (__nv_bfloat16*)0, (__nv_bfloat16*)0,
        gru_bih, (const float*)0, MROWS, 3072, DD, DD, 0);
    gru_kernel<<<GRU_CTAS, 192>>>(gig, gru_whh, gru_bhh, xg, xhi, xlo);

    // join layer-weight stream, run MLP
    cudaStreamWaitEvent(0, ev1, 0);
    for (int l = 0; l < 4; l++) {
        bgemm<0, true, true, true><<<dim3(NNH / 128, MROWS / 128, 1), 256, 61440>>>(
            xhi, xlo, qsyn + (size_t)l * NNH * DD, (const __nv_bfloat16*)0,
            (float*)0, hhi, hlo, syn_b + (size_t)l * NNH, (const float*)0,
            MROWS, NNH, DD, DD, 2 + l);
        bgemm<0, true, false, false><<<dim3(DD / 128, MROWS / 128, 4), 256, 61440>>>(
            hhi, hlo, qout + (size_t)l * DD * NNH, (const __nv_bfloat16*)0,
            psg, (__nv_bfloat16*)0, (__nv_bfloat16*)0, (const float*)0, (const float*)0,
            MROWS, DD, NNH, NNH / 4, 6 + l);
        ln_red<<<MROWS, 256>>>(out_b + (size_t)l * DD, xg, xhi, xlo,
                               ln_g + (size_t)l * DD, ln_b + (size_t)l * DD);
    }

    // join head stream, final LN + head
    cudaStreamWaitEvent(0, ev2, 0);
    ln_kernel<<<MROWS, 256>>>(xg, yg, yhi, ylo, on_g, on_b);
    bgemm<0, true, false, false><<<dim3(VV / 128, MROWS / 128, 1), 256, 61440>>>(
        yhi, ylo, qhead, (const __nv_bfloat16*)0,
        logits, (__nv_bfloat16*)0, (__nv_bfloat16*)0, head_b, (const float*)0,
        MROWS, VV, DD, DD, 1);
}